// round 3
// baseline (speedup 1.0000x reference)
#include <cuda_runtime.h>
#include <math.h>

#define BB 4
#define CC 256
#define NN 4096

// Scratch: token-major projections [B][N][C]
static __device__ float g_Q[BB * NN * CC];
static __device__ float g_K[BB * NN * CC];   // k + pos folded in
static __device__ float g_V[BB * NN * CC];

// XOR swizzle for [row][64-col] smem tiles: permutes float4-groups within a row
// so that column-strided (transposed) scalar writes spread across banks while
// float4 reads of 4 consecutive cols stay contiguous & 16B aligned.
__device__ __forceinline__ int swz(int row, int col) {
    return row * 64 + ((((col >> 2) ^ ((row >> 2) & 15))) << 2) + (col & 3);
}
__device__ __forceinline__ int swz4(int row, int g4) {
    return row * 64 + (((g4) ^ ((row >> 2) & 15)) << 2);
}

// ---------------------------------------------------------------------------
// Projection kernel: out[b][n][o] = sum_c W[o][c] * x[b][c][n] + bias[o] (+pos)
// grid: (N/64, C/64, B*3); block: 256 threads; each thread: 4x4 of a 64x64 tile
// ---------------------------------------------------------------------------
__global__ __launch_bounds__(256) void proj_kernel(
    const float* __restrict__ x,
    const float* __restrict__ Wq, const float* __restrict__ bq,
    const float* __restrict__ Wk, const float* __restrict__ bk,
    const float* __restrict__ Wv, const float* __restrict__ bv,
    const float* __restrict__ rel_h, const float* __restrict__ rel_w)
{
    __shared__ float Xs[16][64];   // [c_local][token]
    __shared__ float Ws[16][68];   // [c_local][o], padded rows (272B, 16B-aligned)

    const int tid = threadIdx.x;
    const int ty = tid >> 4, tx = tid & 15;
    const int n0 = blockIdx.x * 64;
    const int o0 = blockIdx.y * 64;
    const int b = blockIdx.z / 3;
    const int which = blockIdx.z % 3;

    const float* Wm   = (which == 0) ? Wq : (which == 1) ? Wk : Wv;
    const float* bias = (which == 0) ? bq : (which == 1) ? bk : bv;
    float* outp       = (which == 0) ? g_Q : (which == 1) ? g_K : g_V;

    const float* xb = x + (size_t)b * CC * NN;

    const int lcl = tid >> 4, lnf = tid & 15;  // Xs load mapping
    const int lo  = tid >> 2, lcf = tid & 3;   // Ws load mapping

    float acc[4][4] = {};

    for (int c0 = 0; c0 < CC; c0 += 16) {
        float4 xv = *(const float4*)&xb[(size_t)(c0 + lcl) * NN + n0 + lnf * 4];
        float4 wv = *(const float4*)&Wm[(o0 + lo) * CC + c0 + lcf * 4];
        *(float4*)&Xs[lcl][lnf * 4] = xv;
        Ws[lcf * 4 + 0][lo] = wv.x;
        Ws[lcf * 4 + 1][lo] = wv.y;
        Ws[lcf * 4 + 2][lo] = wv.z;
        Ws[lcf * 4 + 3][lo] = wv.w;
        __syncthreads();
        #pragma unroll
        for (int kk = 0; kk < 16; kk++) {
            float4 a4 = *(const float4*)&Xs[kk][ty * 4];
            float4 w4 = *(const float4*)&Ws[kk][tx * 4];
            float a[4] = {a4.x, a4.y, a4.z, a4.w};
            float w[4] = {w4.x, w4.y, w4.z, w4.w};
            #pragma unroll
            for (int i = 0; i < 4; i++)
                #pragma unroll
                for (int j = 0; j < 4; j++)
                    acc[i][j] += a[i] * w[j];
        }
        __syncthreads();
    }

    float bs[4];
    #pragma unroll
    for (int j = 0; j < 4; j++) bs[j] = bias[o0 + tx * 4 + j];

    #pragma unroll
    for (int i = 0; i < 4; i++) {
        int n = n0 + ty * 4 + i;
        float r[4];
        #pragma unroll
        for (int j = 0; j < 4; j++) {
            r[j] = acc[i][j] + bs[j];
            if (which == 1) {
                // pos[c, n] = rel_h[c, n/W] + rel_w[c, n%W], W=H=64
                int c = o0 + tx * 4 + j;
                r[j] += rel_h[c * 64 + (n >> 6)] + rel_w[c * 64 + (n & 63)];
            }
        }
        float4 st = {r[0], r[1], r[2], r[3]};
        *(float4*)&outp[((size_t)b * NN + n) * CC + o0 + tx * 4] = st;
    }
}

// ---------------------------------------------------------------------------
// Flash attention (fp32 SIMT) + residual epilogue.
// grid: (N/64, B); block 256 (16x16 thread tiles).
// Per block: 64 queries, loop over 64 key tiles of 64.
// smem: Qs[256][64] swz | Ks[256][64] swz | Vs[64][256] | Ps[64][64] swz
// ---------------------------------------------------------------------------
__global__ __launch_bounds__(256, 1) void attn_kernel(
    const float* __restrict__ x,
    const float* __restrict__ gamma,
    float* __restrict__ out)
{
    extern __shared__ float sm[];
    float* Qs = sm;              // 16384 floats (transposed, swizzled)
    float* Ks = sm + 16384;      // 16384
    float* Vs = sm + 32768;      // 16384, direct [n][d]
    float* Ps = sm + 49152;      // 4096, [key][row] swizzled

    const int tid = threadIdx.x;
    const int ty = tid >> 4, tx = tid & 15;
    const int m0 = blockIdx.x * 64;
    const int b  = blockIdx.y;

    const float* Qg = g_Q + ((size_t)b * NN + m0) * CC;
    const float* Kg = g_K + (size_t)b * NN * CC;
    const float* Vg = g_V + (size_t)b * NN * CC;

    const int ltok = tid >> 6;   // 0..3
    const int lcf  = tid & 63;   // 0..63

    // Load Q tile transposed into Qs[c][token]
    #pragma unroll
    for (int p = 0; p < 16; p++) {
        int tok = ltok + p * 4;
        float4 v = *(const float4*)&Qg[tok * CC + lcf * 4];
        Qs[swz(lcf * 4 + 0, tok)] = v.x;
        Qs[swz(lcf * 4 + 1, tok)] = v.y;
        Qs[swz(lcf * 4 + 2, tok)] = v.z;
        Qs[swz(lcf * 4 + 3, tok)] = v.w;
    }

    // O accumulator: rows ty*4+i, cols d = 64*j + tx*4 + q  -> o[i][j*4+q]
    float o[4][16];
    #pragma unroll
    for (int i = 0; i < 4; i++)
        #pragma unroll
        for (int j = 0; j < 16; j++) o[i][j] = 0.0f;
    float mrow[4] = {-INFINITY, -INFINITY, -INFINITY, -INFINITY};
    float lrow[4] = {0.0f, 0.0f, 0.0f, 0.0f};

    for (int nt = 0; nt < 64; nt++) {
        const float* Kt = Kg + (size_t)nt * 64 * CC;
        const float* Vt = Vg + (size_t)nt * 64 * CC;

        __syncthreads();   // previous PV done (and Q load on first iter)
        #pragma unroll
        for (int p = 0; p < 16; p++) {
            int tok = ltok + p * 4;
            float4 kv = *(const float4*)&Kt[tok * CC + lcf * 4];
            Ks[swz(lcf * 4 + 0, tok)] = kv.x;
            Ks[swz(lcf * 4 + 1, tok)] = kv.y;
            Ks[swz(lcf * 4 + 2, tok)] = kv.z;
            Ks[swz(lcf * 4 + 3, tok)] = kv.w;
            float4 vv = *(const float4*)&Vt[tok * CC + lcf * 4];
            *(float4*)&Vs[tok * CC + lcf * 4] = vv;
        }
        __syncthreads();

        // S[4][4] = Q(rows ty*4..) . K(cols tx*4..) over 256 dims
        float s[4][4] = {};
        #pragma unroll 8
        for (int kk = 0; kk < CC; kk++) {
            float4 q4 = *(const float4*)&Qs[swz4(kk, ty)];
            float4 k4 = *(const float4*)&Ks[swz4(kk, tx)];
            float q[4] = {q4.x, q4.y, q4.z, q4.w};
            float k[4] = {k4.x, k4.y, k4.z, k4.w};
            #pragma unroll
            for (int i = 0; i < 4; i++)
                #pragma unroll
                for (int j = 0; j < 4; j++)
                    s[i][j] += q[i] * k[j];
        }

        // Online softmax (row stats across the 16 tx lanes)
        #pragma unroll
        for (int i = 0; i < 4; i++) {
            float rm = fmaxf(fmaxf(s[i][0], s[i][1]), fmaxf(s[i][2], s[i][3]));
            #pragma unroll
            for (int off = 1; off < 16; off <<= 1)
                rm = fmaxf(rm, __shfl_xor_sync(0xffffffffu, rm, off));
            float mnew = fmaxf(mrow[i], rm);
            float p0 = __expf(s[i][0] - mnew);
            float p1 = __expf(s[i][1] - mnew);
            float p2 = __expf(s[i][2] - mnew);
            float p3 = __expf(s[i][3] - mnew);
            float rs = (p0 + p1) + (p2 + p3);
            #pragma unroll
            for (int off = 1; off < 16; off <<= 1)
                rs += __shfl_xor_sync(0xffffffffu, rs, off);
            float scale = __expf(mrow[i] - mnew);
            lrow[i] = lrow[i] * scale + rs;
            if (scale != 1.0f) {
                #pragma unroll
                for (int j = 0; j < 16; j++) o[i][j] *= scale;
            }
            mrow[i] = mnew;
            int r = ty * 4 + i;
            Ps[swz(tx * 4 + 0, r)] = p0;
            Ps[swz(tx * 4 + 1, r)] = p1;
            Ps[swz(tx * 4 + 2, r)] = p2;
            Ps[swz(tx * 4 + 3, r)] = p3;
        }
        __syncthreads();

        // O += P @ V
        #pragma unroll 2
        for (int n = 0; n < 64; n++) {
            float4 p4 = *(const float4*)&Ps[swz4(n, ty)];
            float pr[4] = {p4.x, p4.y, p4.z, p4.w};
            #pragma unroll
            for (int j = 0; j < 4; j++) {
                float4 v4 = *(const float4*)&Vs[n * CC + 64 * j + tx * 4];
                float vv[4] = {v4.x, v4.y, v4.z, v4.w};
                #pragma unroll
                for (int i = 0; i < 4; i++) {
                    o[i][j * 4 + 0] += pr[i] * vv[0];
                    o[i][j * 4 + 1] += pr[i] * vv[1];
                    o[i][j * 4 + 2] += pr[i] * vv[2];
                    o[i][j * 4 + 3] += pr[i] * vv[3];
                }
            }
        }
    }

    float inv[4];
    #pragma unroll
    for (int i = 0; i < 4; i++) inv[i] = 1.0f / lrow[i];

    // Stage O transposed [d][token] in smem (reuse Qs) for coalesced output
    __syncthreads();
    float* Os = Qs;
    #pragma unroll
    for (int j = 0; j < 4; j++)
        #pragma unroll
        for (int q = 0; q < 4; q++) {
            int d = 64 * j + tx * 4 + q;
            #pragma unroll
            for (int i = 0; i < 4; i++)
                Os[swz(d, ty * 4 + i)] = o[i][j * 4 + q] * inv[i];
        }
    __syncthreads();

    const float g = gamma[0];
    const int ed  = tid >> 4;   // 0..15
    const int et4 = tid & 15;   // token float4 group
    #pragma unroll
    for (int p = 0; p < 16; p++) {
        int d = ed + p * 16;
        float4 ov = *(const float4*)&Os[swz4(d, et4)];
        size_t gi = ((size_t)b * CC + d) * NN + m0 + et4 * 4;
        float4 xv = *(const float4*)&x[gi];
        float4 r = {g * ov.x + xv.x, g * ov.y + xv.y,
                    g * ov.z + xv.z, g * ov.w + xv.w};
        *(float4*)&out[gi] = r;
    }
}

// ---------------------------------------------------------------------------
extern "C" void kernel_launch(void* const* d_in, const int* in_sizes, int n_in,
                              void* d_out, int out_size)
{
    (void)in_sizes; (void)n_in; (void)out_size;
    const float* x     = (const float*)d_in[0];
    const float* Wq    = (const float*)d_in[1];
    const float* bq    = (const float*)d_in[2];
    const float* Wk    = (const float*)d_in[3];
    const float* bk    = (const float*)d_in[4];
    const float* Wv    = (const float*)d_in[5];
    const float* bv    = (const float*)d_in[6];
    const float* rel_h = (const float*)d_in[7];
    const float* rel_w = (const float*)d_in[8];
    const float* gamma = (const float*)d_in[9];
    float* out = (float*)d_out;

    const int smem_bytes = 53248 * 4;   // 208 KB
    cudaFuncSetAttribute(attn_kernel,
                         cudaFuncAttributeMaxDynamicSharedMemorySize, smem_bytes);

    proj_kernel<<<dim3(64, 4, 12), 256>>>(x, Wq, bq, Wk, bk, Wv, bv, rel_h, rel_w);
    attn_kernel<<<dim3(64, 4), 256, smem_bytes>>>(x, gamma, out);
}

// round 6
// speedup vs baseline: 1.6409x; 1.6409x over previous
#include <cuda_runtime.h>
#include <math.h>

#define BB 4
#define CC 256
#define NN 4096

// Scratch: token-major projections [B][N][C]
static __device__ float g_Q[BB * NN * CC];
static __device__ float g_K[BB * NN * CC];   // k + pos folded in
static __device__ float g_V[BB * NN * CC];

// XOR swizzle for [row][64-col] smem tiles: permutes float4-groups within a row
// so that column-strided (transposed) scalar writes spread across banks while
// float4 reads of 4 consecutive cols stay contiguous & 16B aligned.
__device__ __forceinline__ int swz(int row, int col) {
    return row * 64 + ((((col >> 2) ^ ((row >> 2) & 15))) << 2) + (col & 3);
}
__device__ __forceinline__ int swz4(int row, int g4) {
    return row * 64 + (((g4) ^ ((row >> 2) & 15)) << 2);
}

// ---------------------------------------------------------------------------
// Projection kernel: out[b][n][o] = sum_c W[o][c] * x[b][c][n] + bias[o] (+pos)
// grid: (N/64, C/64, B*3); block: 256 threads; each thread: 4x4 of a 64x64 tile
// ---------------------------------------------------------------------------
__global__ __launch_bounds__(256) void proj_kernel(
    const float* __restrict__ x,
    const float* __restrict__ Wq, const float* __restrict__ bq,
    const float* __restrict__ Wk, const float* __restrict__ bk,
    const float* __restrict__ Wv, const float* __restrict__ bv,
    const float* __restrict__ rel_h, const float* __restrict__ rel_w)
{
    __shared__ float Xs[16][64];   // [c_local][token]
    __shared__ float Ws[16][68];   // [c_local][o], padded rows (272B, 16B-aligned)

    const int tid = threadIdx.x;
    const int ty = tid >> 4, tx = tid & 15;
    const int n0 = blockIdx.x * 64;
    const int o0 = blockIdx.y * 64;
    const int b = blockIdx.z / 3;
    const int which = blockIdx.z % 3;

    const float* Wm   = (which == 0) ? Wq : (which == 1) ? Wk : Wv;
    const float* bias = (which == 0) ? bq : (which == 1) ? bk : bv;
    float* outp       = (which == 0) ? g_Q : (which == 1) ? g_K : g_V;

    const float* xb = x + (size_t)b * CC * NN;

    const int lcl = tid >> 4, lnf = tid & 15;  // Xs load mapping
    const int lo  = tid >> 2, lcf = tid & 3;   // Ws load mapping

    float acc[4][4] = {};

    for (int c0 = 0; c0 < CC; c0 += 16) {
        float4 xv = *(const float4*)&xb[(size_t)(c0 + lcl) * NN + n0 + lnf * 4];
        float4 wv = *(const float4*)&Wm[(o0 + lo) * CC + c0 + lcf * 4];
        *(float4*)&Xs[lcl][lnf * 4] = xv;
        Ws[lcf * 4 + 0][lo] = wv.x;
        Ws[lcf * 4 + 1][lo] = wv.y;
        Ws[lcf * 4 + 2][lo] = wv.z;
        Ws[lcf * 4 + 3][lo] = wv.w;
        __syncthreads();
        #pragma unroll
        for (int kk = 0; kk < 16; kk++) {
            float4 a4 = *(const float4*)&Xs[kk][ty * 4];
            float4 w4 = *(const float4*)&Ws[kk][tx * 4];
            float a[4] = {a4.x, a4.y, a4.z, a4.w};
            float w[4] = {w4.x, w4.y, w4.z, w4.w};
            #pragma unroll
            for (int i = 0; i < 4; i++)
                #pragma unroll
                for (int j = 0; j < 4; j++)
                    acc[i][j] += a[i] * w[j];
        }
        __syncthreads();
    }

    float bs[4];
    #pragma unroll
    for (int j = 0; j < 4; j++) bs[j] = bias[o0 + tx * 4 + j];

    #pragma unroll
    for (int i = 0; i < 4; i++) {
        int n = n0 + ty * 4 + i;
        float r[4];
        #pragma unroll
        for (int j = 0; j < 4; j++) {
            r[j] = acc[i][j] + bs[j];
            if (which == 1) {
                // pos[c, n] = rel_h[c, n/W] + rel_w[c, n%W], W=H=64
                int c = o0 + tx * 4 + j;
                r[j] += rel_h[c * 64 + (n >> 6)] + rel_w[c * 64 + (n & 63)];
            }
        }
        float4 st = {r[0], r[1], r[2], r[3]};
        *(float4*)&outp[((size_t)b * NN + n) * CC + o0 + tx * 4] = st;
    }
}

// ---------------------------------------------------------------------------
// Flash attention (fp32 SIMT) + residual epilogue.
// grid: (N/64, B); block 256 (16x16 thread tiles).
// Per block: 64 queries, loop over 64 key tiles of 64.
// smem: Qs[256][64] swz | Ks[256][64] swz | Vs[64][256] | Ps[64][64] swz
// ---------------------------------------------------------------------------
__global__ __launch_bounds__(256, 1) void attn_kernel(
    const float* __restrict__ x,
    const float* __restrict__ gamma,
    float* __restrict__ out)
{
    extern __shared__ float sm[];
    float* Qs = sm;              // 16384 floats (transposed, swizzled)
    float* Ks = sm + 16384;      // 16384
    float* Vs = sm + 32768;      // 16384, direct [n][d]
    float* Ps = sm + 49152;      // 4096, [key][row] swizzled

    const int tid = threadIdx.x;
    const int ty = tid >> 4, tx = tid & 15;
    const int m0 = blockIdx.x * 64;
    const int b  = blockIdx.y;

    const float* Qg = g_Q + ((size_t)b * NN + m0) * CC;
    const float* Kg = g_K + (size_t)b * NN * CC;
    const float* Vg = g_V + (size_t)b * NN * CC;

    const int ltok = tid >> 6;   // 0..3
    const int lcf  = tid & 63;   // 0..63

    // Load Q tile transposed into Qs[c][token]
    #pragma unroll
    for (int p = 0; p < 16; p++) {
        int tok = ltok + p * 4;
        float4 v = *(const float4*)&Qg[tok * CC + lcf * 4];
        Qs[swz(lcf * 4 + 0, tok)] = v.x;
        Qs[swz(lcf * 4 + 1, tok)] = v.y;
        Qs[swz(lcf * 4 + 2, tok)] = v.z;
        Qs[swz(lcf * 4 + 3, tok)] = v.w;
    }

    // O accumulator: rows ty*4+i, cols d = 64*j + tx*4 + q  -> o[i][j*4+q]
    float o[4][16];
    #pragma unroll
    for (int i = 0; i < 4; i++)
        #pragma unroll
        for (int j = 0; j < 16; j++) o[i][j] = 0.0f;
    float mrow[4] = {-INFINITY, -INFINITY, -INFINITY, -INFINITY};
    float lrow[4] = {0.0f, 0.0f, 0.0f, 0.0f};

    for (int nt = 0; nt < 64; nt++) {
        const float* Kt = Kg + (size_t)nt * 64 * CC;
        const float* Vt = Vg + (size_t)nt * 64 * CC;

        __syncthreads();   // previous PV done (and Q load on first iter)
        #pragma unroll
        for (int p = 0; p < 16; p++) {
            int tok = ltok + p * 4;
            float4 kv = *(const float4*)&Kt[tok * CC + lcf * 4];
            Ks[swz(lcf * 4 + 0, tok)] = kv.x;
            Ks[swz(lcf * 4 + 1, tok)] = kv.y;
            Ks[swz(lcf * 4 + 2, tok)] = kv.z;
            Ks[swz(lcf * 4 + 3, tok)] = kv.w;
            float4 vv = *(const float4*)&Vt[tok * CC + lcf * 4];
            *(float4*)&Vs[tok * CC + lcf * 4] = vv;
        }
        __syncthreads();

        // S[4][4] = Q(rows ty*4..) . K(cols tx*4..) over 256 dims
        float s[4][4] = {};
        #pragma unroll 8
        for (int kk = 0; kk < CC; kk++) {
            float4 q4 = *(const float4*)&Qs[swz4(kk, ty)];
            float4 k4 = *(const float4*)&Ks[swz4(kk, tx)];
            float q[4] = {q4.x, q4.y, q4.z, q4.w};
            float k[4] = {k4.x, k4.y, k4.z, k4.w};
            #pragma unroll
            for (int i = 0; i < 4; i++)
                #pragma unroll
                for (int j = 0; j < 4; j++)
                    s[i][j] += q[i] * k[j];
        }

        // Online softmax (row stats across the 16 tx lanes)
        #pragma unroll
        for (int i = 0; i < 4; i++) {
            float rm = fmaxf(fmaxf(s[i][0], s[i][1]), fmaxf(s[i][2], s[i][3]));
            #pragma unroll
            for (int off = 1; off < 16; off <<= 1)
                rm = fmaxf(rm, __shfl_xor_sync(0xffffffffu, rm, off));
            float mnew = fmaxf(mrow[i], rm);
            float p0 = __expf(s[i][0] - mnew);
            float p1 = __expf(s[i][1] - mnew);
            float p2 = __expf(s[i][2] - mnew);
            float p3 = __expf(s[i][3] - mnew);
            float rs = (p0 + p1) + (p2 + p3);
            #pragma unroll
            for (int off = 1; off < 16; off <<= 1)
                rs += __shfl_xor_sync(0xffffffffu, rs, off);
            float scale = __expf(mrow[i] - mnew);
            lrow[i] = lrow[i] * scale + rs;
            if (scale != 1.0f) {
                #pragma unroll
                for (int j = 0; j < 16; j++) o[i][j] *= scale;
            }
            mrow[i] = mnew;
            int r = ty * 4 + i;
            Ps[swz(tx * 4 + 0, r)] = p0;
            Ps[swz(tx * 4 + 1, r)] = p1;
            Ps[swz(tx * 4 + 2, r)] = p2;
            Ps[swz(tx * 4 + 3, r)] = p3;
        }
        __syncthreads();

        // O += P @ V
        #pragma unroll 2
        for (int n = 0; n < 64; n++) {
            float4 p4 = *(const float4*)&Ps[swz4(n, ty)];
            float pr[4] = {p4.x, p4.y, p4.z, p4.w};
            #pragma unroll
            for (int j = 0; j < 4; j++) {
                float4 v4 = *(const float4*)&Vs[n * CC + 64 * j + tx * 4];
                float vv[4] = {v4.x, v4.y, v4.z, v4.w};
                #pragma unroll
                for (int i = 0; i < 4; i++) {
                    o[i][j * 4 + 0] += pr[i] * vv[0];
                    o[i][j * 4 + 1] += pr[i] * vv[1];
                    o[i][j * 4 + 2] += pr[i] * vv[2];
                    o[i][j * 4 + 3] += pr[i] * vv[3];
                }
            }
        }
    }

    float inv[4];
    #pragma unroll
    for (int i = 0; i < 4; i++) inv[i] = 1.0f / lrow[i];

    // Stage O transposed [d][token] in smem (reuse Qs) for coalesced output
    __syncthreads();
    float* Os = Qs;
    #pragma unroll
    for (int j = 0; j < 4; j++)
        #pragma unroll
        for (int q = 0; q < 4; q++) {
            int d = 64 * j + tx * 4 + q;
            #pragma unroll
            for (int i = 0; i < 4; i++)
                Os[swz(d, ty * 4 + i)] = o[i][j * 4 + q] * inv[i];
        }
    __syncthreads();

    const float g = gamma[0];
    const int ed  = tid >> 4;   // 0..15
    const int et4 = tid & 15;   // token float4 group
    #pragma unroll
    for (int p = 0; p < 16; p++) {
        int d = ed + p * 16;
        float4 ov = *(const float4*)&Os[swz4(d, et4)];
        size_t gi = ((size_t)b * CC + d) * NN + m0 + et4 * 4;
        float4 xv = *(const float4*)&x[gi];
        float4 r = {g * ov.x + xv.x, g * ov.y + xv.y,
                    g * ov.z + xv.z, g * ov.w + xv.w};
        *(float4*)&out[gi] = r;
    }
}

// ---------------------------------------------------------------------------
extern "C" void kernel_launch(void* const* d_in, const int* in_sizes, int n_in,
                              void* d_out, int out_size)
{
    (void)in_sizes; (void)n_in; (void)out_size;
    const float* x     = (const float*)d_in[0];
    const float* Wq    = (const float*)d_in[1];
    const float* bq    = (const float*)d_in[2];
    const float* Wk    = (const float*)d_in[3];
    const float* bk    = (const float*)d_in[4];
    const float* Wv    = (const float*)d_in[5];
    const float* bv    = (const float*)d_in[6];
    const float* rel_h = (const float*)d_in[7];
    const float* rel_w = (const float*)d_in[8];
    const float* gamma = (const float*)d_in[9];
    float* out = (float*)d_out;

    const int smem_bytes = 53248 * 4;   // 208 KB
    cudaFuncSetAttribute(attn_kernel,
                         cudaFuncAttributeMaxDynamicSharedMemorySize, smem_bytes);

    proj_kernel<<<dim3(64, 4, 12), 256>>>(x, Wq, bq, Wk, bk, Wv, bv, rel_h, rel_w);
    attn_kernel<<<dim3(64, 4), 256, smem_bytes>>>(x, gamma, out);
}

// round 13
// speedup vs baseline: 4.4683x; 2.7231x over previous
#include <cuda_runtime.h>
#include <cuda_bf16.h>
#include <stdint.h>
#include <math.h>

#define BB 4
#define CC 256
#define NN 4096

// bf16 hi/lo split operands
static __device__ __nv_bfloat16 g_Qh[BB*NN*CC], g_Ql[BB*NN*CC];   // token-major [b][n][c]
static __device__ __nv_bfloat16 g_Kh[BB*NN*CC], g_Kl[BB*NN*CC];   // token-major (pos folded)
static __device__ __nv_bfloat16 g_Vh[BB*NN*CC], g_Vl[BB*NN*CC];   // channel-major [b][c][n]

// ===================== helpers (base-target ISA only) =====================
__device__ __forceinline__ uint32_t smem_u32(const void* p) {
    uint32_t a;
    asm("{ .reg .u64 t; cvta.to.shared.u64 t, %1; cvt.u32.u64 %0, t; }" : "=r"(a) : "l"(p));
    return a;
}
__device__ __forceinline__ void ldsm4(uint32_t a, uint32_t r[4]) {
    asm volatile("ldmatrix.sync.aligned.m8n8.x4.shared.b16 {%0,%1,%2,%3}, [%4];"
        : "=r"(r[0]), "=r"(r[1]), "=r"(r[2]), "=r"(r[3]) : "r"(a));
}
__device__ __forceinline__ void mma16816(float d[4], const uint32_t a[4], uint32_t b0, uint32_t b1) {
    asm volatile("mma.sync.aligned.m16n8k16.row.col.f32.bf16.bf16.f32 "
        "{%0,%1,%2,%3}, {%4,%5,%6,%7}, {%8,%9}, {%0,%1,%2,%3};"
        : "+f"(d[0]), "+f"(d[1]), "+f"(d[2]), "+f"(d[3])
        : "r"(a[0]), "r"(a[1]), "r"(a[2]), "r"(a[3]), "r"(b0), "r"(b1));
}
__device__ __forceinline__ void cp16(uint32_t dst, const void* src) {
    asm volatile("cp.async.cg.shared.global [%0], [%1], 16;" :: "r"(dst), "l"(src));
}
#define CPC()  asm volatile("cp.async.commit_group;" ::: "memory")
#define CPW(n) asm volatile("cp.async.wait_group %0;" :: "n"(n) : "memory")

__device__ __forceinline__ uint32_t bfpack(__nv_bfloat16 a, __nv_bfloat16 b) {
    return (uint32_t)__bfloat16_as_ushort(a) | ((uint32_t)__bfloat16_as_ushort(b) << 16);
}

// smem byte offsets
#define QH_O 0
#define QL_O 33792
#define KH_O 67584
#define KL_O 101376
#define VH_O 135168
#define VL_O 172032
#define PH_O 208896
#define PL_O 218112
#define ST_O 227328
#define SMEM_BYTES 229376
// deltas
#define D_QL 33792
#define D_KL 33792
#define D_VL 36864
#define D_PL 9216

// ---------------------------------------------------------------------------
// Projection: out[b][n][o] = sum_c W[o][c] x[b][c][n] + bias (+pos for K)
// Emits bf16 hi/lo: Q,K token-major; V channel-major (smem transpose).
// ---------------------------------------------------------------------------
__global__ __launch_bounds__(256) void proj_kernel(
    const float* __restrict__ x,
    const float* __restrict__ Wq, const float* __restrict__ bq,
    const float* __restrict__ Wk, const float* __restrict__ bk,
    const float* __restrict__ Wv, const float* __restrict__ bv,
    const float* __restrict__ rel_h, const float* __restrict__ rel_w)
{
    __shared__ float Xs[16][64];
    __shared__ float Ws[16][68];
    __shared__ float Ts[64][65];

    const int tid = threadIdx.x;
    const int ty = tid >> 4, tx = tid & 15;
    const int n0 = blockIdx.x * 64;
    const int o0 = blockIdx.y * 64;
    const int b = blockIdx.z / 3;
    const int which = blockIdx.z % 3;

    const float* Wm   = (which == 0) ? Wq : (which == 1) ? Wk : Wv;
    const float* bias = (which == 0) ? bq : (which == 1) ? bk : bv;
    const float* xb = x + (size_t)b * CC * NN;

    const int lcl = tid >> 4, lnf = tid & 15;
    const int lo_ = tid >> 2, lcf = tid & 3;

    float acc[4][4] = {};
    for (int c0 = 0; c0 < CC; c0 += 16) {
        float4 xv = *(const float4*)&xb[(size_t)(c0 + lcl) * NN + n0 + lnf * 4];
        float4 wv = *(const float4*)&Wm[(o0 + lo_) * CC + c0 + lcf * 4];
        *(float4*)&Xs[lcl][lnf * 4] = xv;
        Ws[lcf * 4 + 0][lo_] = wv.x;
        Ws[lcf * 4 + 1][lo_] = wv.y;
        Ws[lcf * 4 + 2][lo_] = wv.z;
        Ws[lcf * 4 + 3][lo_] = wv.w;
        __syncthreads();
        #pragma unroll
        for (int kk = 0; kk < 16; kk++) {
            float4 a4 = *(const float4*)&Xs[kk][ty * 4];
            float4 w4 = *(const float4*)&Ws[kk][tx * 4];
            float a[4] = {a4.x, a4.y, a4.z, a4.w};
            float w[4] = {w4.x, w4.y, w4.z, w4.w};
            #pragma unroll
            for (int i = 0; i < 4; i++)
                #pragma unroll
                for (int j = 0; j < 4; j++)
                    acc[i][j] += a[i] * w[j];
        }
        __syncthreads();
    }

    float bs[4];
    #pragma unroll
    for (int j = 0; j < 4; j++) bs[j] = bias[o0 + tx * 4 + j];

    if (which < 2) {
        __nv_bfloat16* H = which ? g_Kh : g_Qh;
        __nv_bfloat16* L = which ? g_Kl : g_Ql;
        #pragma unroll
        for (int i = 0; i < 4; i++) {
            int n = n0 + ty * 4 + i;
            uint32_t hw[2], lw[2];
            #pragma unroll
            for (int jj = 0; jj < 2; jj++) {
                float r0 = acc[i][jj*2]   + bs[jj*2];
                float r1 = acc[i][jj*2+1] + bs[jj*2+1];
                if (which == 1) {
                    int c0 = o0 + tx * 4 + jj*2;
                    r0 += rel_h[c0 * 64 + (n >> 6)] + rel_w[c0 * 64 + (n & 63)];
                    r1 += rel_h[(c0+1) * 64 + (n >> 6)] + rel_w[(c0+1) * 64 + (n & 63)];
                }
                __nv_bfloat16 h0 = __float2bfloat16_rn(r0), h1 = __float2bfloat16_rn(r1);
                hw[jj] = bfpack(h0, h1);
                lw[jj] = bfpack(__float2bfloat16_rn(r0 - __bfloat162float(h0)),
                                __float2bfloat16_rn(r1 - __bfloat162float(h1)));
            }
            size_t gi = ((size_t)b * NN + n) * CC + o0 + tx * 4;
            *(uint2*)&H[gi] = make_uint2(hw[0], hw[1]);
            *(uint2*)&L[gi] = make_uint2(lw[0], lw[1]);
        }
    } else {
        // V: transpose to channel-major via smem
        #pragma unroll
        for (int i = 0; i < 4; i++)
            #pragma unroll
            for (int j = 0; j < 4; j++)
                Ts[tx * 4 + j][ty * 4 + i] = acc[i][j] + bs[j];
        __syncthreads();
        int cl = tid >> 2, n4 = tid & 3;
        uint32_t hw[8], lw[8];
        #pragma unroll
        for (int k = 0; k < 8; k++) {
            float v0 = Ts[cl][n4 * 16 + 2*k];
            float v1 = Ts[cl][n4 * 16 + 2*k + 1];
            __nv_bfloat16 h0 = __float2bfloat16_rn(v0), h1 = __float2bfloat16_rn(v1);
            hw[k] = bfpack(h0, h1);
            lw[k] = bfpack(__float2bfloat16_rn(v0 - __bfloat162float(h0)),
                           __float2bfloat16_rn(v1 - __bfloat162float(h1)));
        }
        size_t gi = ((size_t)b * CC + o0 + cl) * NN + n0 + n4 * 16;
        *(uint4*)&g_Vh[gi]     = make_uint4(hw[0], hw[1], hw[2], hw[3]);
        *(uint4*)&g_Vh[gi + 8] = make_uint4(hw[4], hw[5], hw[6], hw[7]);
        *(uint4*)&g_Vl[gi]     = make_uint4(lw[0], lw[1], lw[2], lw[3]);
        *(uint4*)&g_Vl[gi + 8] = make_uint4(lw[4], lw[5], lw[6], lw[7]);
    }
}

// ---------------------------------------------------------------------------
// HMMA (mma.sync bf16 split) flash attention. grid (64, 4), 256 threads.
// Per CTA: 64 queries; loop 64 tiles of 64 keys. O in regs, lazy rebase.
// B-operands (K, V) are k-contiguous in smem => NON-trans ldmatrix.
// ---------------------------------------------------------------------------
__global__ __launch_bounds__(256, 1) void attn_kernel(
    const float* __restrict__ x,
    const float* __restrict__ gamma,
    float* __restrict__ out)
{
    extern __shared__ char sm[];
    const uint32_t sb = smem_u32(sm);
    const int tid = threadIdx.x;
    const int wid = tid >> 5, ln = tid & 31;
    const int g = wid & 3, h = wid >> 2;
    const int b = blockIdx.y, m0 = blockIdx.x * 64;

    float* rowM  = (float*)(sm + ST_O);          // [64]
    float* rowL  = rowM + 64;                    // [64]
    float* rowF  = rowM + 128;                   // [64]
    float* halfM = rowM + 192;                   // [2][64]
    float* halfS = rowM + 320;                   // [2][64]

    const __nv_bfloat16* Qhg = g_Qh + ((size_t)b * NN + m0) * CC;
    const __nv_bfloat16* Qlg = g_Ql + ((size_t)b * NN + m0) * CC;

    auto loadK = [&](int nt) {
        const char* kh = (const char*)(g_Kh + ((size_t)b * NN + nt * 64) * CC);
        const char* kl = (const char*)(g_Kl + ((size_t)b * NN + nt * 64) * CC);
        for (int q = tid; q < 2048; q += 256) {
            int row = q >> 5, seg = q & 31;
            uint32_t d = sb + KH_O + row * 528 + seg * 16;
            cp16(d,        kh + row * 512 + seg * 16);
            cp16(d + D_KL, kl + row * 512 + seg * 16);
        }
    };
    auto loadV = [&](int nt) {
        const char* vh = (const char*)(g_Vh + (size_t)b * CC * NN + nt * 64);
        const char* vl = (const char*)(g_Vl + (size_t)b * CC * NN + nt * 64);
        for (int q = tid; q < 2048; q += 256) {
            int c = q >> 3, seg = q & 7;
            uint32_t d = sb + VH_O + c * 144 + seg * 16;
            cp16(d,        vh + (size_t)c * 8192 + seg * 16);
            cp16(d + D_VL, vl + (size_t)c * 8192 + seg * 16);
        }
    };

    if (tid < 64) rowL[tid] = 0.0f;

    // prologue: Q, K0, V0
    for (int q = tid; q < 2048; q += 256) {
        int row = q >> 5, seg = q & 31;
        uint32_t d = sb + QH_O + row * 528 + seg * 16;
        cp16(d,        (const char*)Qhg + row * 512 + seg * 16);
        cp16(d + D_QL, (const char*)Qlg + row * 512 + seg * 16);
    }
    CPC();
    loadK(0); CPC();
    loadV(0); CPC();

    // per-lane ldmatrix address components (same pattern for A and B operands)
    const uint32_t rowsel = ((ln >> 4) << 3) + (ln & 7);
    const uint32_t colsel = ((ln >> 3) & 1) << 4;          // 0/16 B
    const uint32_t asel   = (ln & 15);
    const uint32_t acol   = (ln >> 4) << 4;                // 0/16 B
    const uint32_t aQh = sb + QH_O + (16*g + asel) * 528 + acol;
    const uint32_t aQl = aQh + D_QL;
    const uint32_t bK0 = sb + KH_O + (32*h + rowsel) * 528 + colsel;
    const uint32_t bK1 = bK0 + 16 * 528;
    const uint32_t aPh = sb + PH_O + (16*g + asel) * 144 + acol;
    const uint32_t bV0 = sb + VH_O + (128*h + rowsel) * 144 + colsel;
    const int rA = 16*g + (ln >> 2), rB = rA + 8;

    float o[16][4];
    #pragma unroll
    for (int t = 0; t < 16; t++)
        #pragma unroll
        for (int j = 0; j < 4; j++) o[t][j] = 0.0f;

    for (int nt = 0; nt < 64; nt++) {
        CPW(1);            // K(nt) (and Q) resident; V(nt) may still be in flight
        __syncthreads();

        // ---- QK: S(64x64) in regs, 3-way split ----
        float s0[4] = {}, s1[4] = {}, s2[4] = {}, s3[4] = {};
        #pragma unroll
        for (int kk = 0; kk < 16; kk++) {
            uint32_t ah[4], al[4], bh0[4], bh1[4], bl0[4], bl1[4];
            const uint32_t ko = kk * 32;
            ldsm4(aQh + ko, ah); ldsm4(aQl + ko, al);
            ldsm4(bK0 + ko, bh0); ldsm4(bK1 + ko, bh1);
            ldsm4(bK0 + D_KL + ko, bl0); ldsm4(bK1 + D_KL + ko, bl1);
            mma16816(s0, ah, bh0[0], bh0[1]); mma16816(s1, ah, bh0[2], bh0[3]);
            mma16816(s2, ah, bh1[0], bh1[1]); mma16816(s3, ah, bh1[2], bh1[3]);
            mma16816(s0, ah, bl0[0], bl0[1]); mma16816(s1, ah, bl0[2], bl0[3]);
            mma16816(s2, ah, bl1[0], bl1[1]); mma16816(s3, ah, bl1[2], bl1[3]);
            mma16816(s0, al, bh0[0], bh0[1]); mma16816(s1, al, bh0[2], bh0[3]);
            mma16816(s2, al, bh1[0], bh1[1]); mma16816(s3, al, bh1[2], bh1[3]);
        }
        __syncthreads();               // everyone done reading K
        if (nt < 63) loadK(nt + 1);
        CPC();

        // ---- softmax (rows rA, rB; this warp owns cols 32h..32h+31) ----
        float mA = fmaxf(fmaxf(s0[0], s0[1]), fmaxf(s1[0], s1[1]));
        mA = fmaxf(mA, fmaxf(fmaxf(s2[0], s2[1]), fmaxf(s3[0], s3[1])));
        float mB = fmaxf(fmaxf(s0[2], s0[3]), fmaxf(s1[2], s1[3]));
        mB = fmaxf(mB, fmaxf(fmaxf(s2[2], s2[3]), fmaxf(s3[2], s3[3])));
        mA = fmaxf(mA, __shfl_xor_sync(0xffffffffu, mA, 1));
        mA = fmaxf(mA, __shfl_xor_sync(0xffffffffu, mA, 2));
        mB = fmaxf(mB, __shfl_xor_sync(0xffffffffu, mB, 1));
        mB = fmaxf(mB, __shfl_xor_sync(0xffffffffu, mB, 2));
        if ((ln & 3) == 0) { halfM[h*64 + rA] = mA; halfM[h*64 + rB] = mB; }
        __syncthreads();
        if (tid < 64) {
            float tm = fmaxf(halfM[tid], halfM[64 + tid]);
            float m, f;
            if (nt == 0) { m = tm; f = 1.0f; }
            else {
                m = rowM[tid];
                if (tm > m + 25.0f) { f = __expf(m - tm); m = tm; }
                else f = 1.0f;
            }
            rowM[tid] = m; rowF[tid] = f;
        }
        __syncthreads();

        const float mrA = rowM[rA], mrB = rowM[rB];
        float pA = 0.0f, pB = 0.0f;
        {
            const uint32_t cbyte = (32*h + 2*(ln & 3)) * 2;
            char* baA = sm + PH_O + rA * 144 + cbyte;
            char* baB = sm + PH_O + rB * 144 + cbyte;
            float* sv[4] = {s0, s1, s2, s3};
            #pragma unroll
            for (int t = 0; t < 4; t++) {
                float p0 = __expf(sv[t][0] - mrA);
                float p1 = __expf(sv[t][1] - mrA);
                float p2 = __expf(sv[t][2] - mrB);
                float p3 = __expf(sv[t][3] - mrB);
                pA += p0 + p1; pB += p2 + p3;
                __nv_bfloat16 h0 = __float2bfloat16_rn(p0), h1 = __float2bfloat16_rn(p1);
                __nv_bfloat16 h2 = __float2bfloat16_rn(p2), h3 = __float2bfloat16_rn(p3);
                *(uint32_t*)(baA + t*16)        = bfpack(h0, h1);
                *(uint32_t*)(baB + t*16)        = bfpack(h2, h3);
                *(uint32_t*)(baA + D_PL + t*16) = bfpack(__float2bfloat16_rn(p0 - __bfloat162float(h0)),
                                                         __float2bfloat16_rn(p1 - __bfloat162float(h1)));
                *(uint32_t*)(baB + D_PL + t*16) = bfpack(__float2bfloat16_rn(p2 - __bfloat162float(h2)),
                                                         __float2bfloat16_rn(p3 - __bfloat162float(h3)));
            }
        }
        pA += __shfl_xor_sync(0xffffffffu, pA, 1);
        pA += __shfl_xor_sync(0xffffffffu, pA, 2);
        pB += __shfl_xor_sync(0xffffffffu, pB, 1);
        pB += __shfl_xor_sync(0xffffffffu, pB, 2);
        if ((ln & 3) == 0) { halfS[h*64 + rA] = pA; halfS[h*64 + rB] = pB; }
        __syncthreads();
        if (tid < 64)
            rowL[tid] = rowL[tid] * rowF[tid] + halfS[tid] + halfS[64 + tid];

        CPW(1);            // V(nt) resident; K(nt+1) may be in flight
        __syncthreads();

        // ---- O lazy rescale + PV (O += P @ V, 3-way split) ----
        const float fA = rowF[rA], fB = rowF[rB];
        #pragma unroll
        for (int t = 0; t < 16; t++) {
            o[t][0] *= fA; o[t][1] *= fA; o[t][2] *= fB; o[t][3] *= fB;
        }
        #pragma unroll
        for (int kk = 0; kk < 4; kk++) {
            uint32_t ph[4], pl[4];
            const uint32_t ko = kk * 32;
            ldsm4(aPh + ko, ph); ldsm4(aPh + D_PL + ko, pl);
            #pragma unroll
            for (int t = 0; t < 8; t++) {
                uint32_t vh[4], vl[4];
                const uint32_t vb = bV0 + t * (16 * 144) + ko;
                ldsm4(vb, vh); ldsm4(vb + D_VL, vl);
                mma16816(o[2*t],   ph, vh[0], vh[1]); mma16816(o[2*t+1], ph, vh[2], vh[3]);
                mma16816(o[2*t],   ph, vl[0], vl[1]); mma16816(o[2*t+1], ph, vl[2], vl[3]);
                mma16816(o[2*t],   pl, vh[0], vh[1]); mma16816(o[2*t+1], pl, vh[2], vh[3]);
            }
        }
        __syncthreads();               // done reading V & P
        if (nt < 63) loadV(nt + 1);
        CPC();
    }

    // ---- epilogue: O/l, transpose through (free) V region, residual ----
    __syncthreads();
    const float invA = 1.0f / rowL[rA];
    const float invB = 1.0f / rowL[rB];
    float* Os = (float*)(sm + VH_O);   // [256 c][68 tok]
    #pragma unroll
    for (int t = 0; t < 16; t++) {
        int c = 128*h + 16*(t >> 1) + 8*(t & 1) + 2*(ln & 3);
        Os[c * 68 + rA]       = o[t][0] * invA;
        Os[(c + 1) * 68 + rA] = o[t][1] * invA;
        Os[c * 68 + rB]       = o[t][2] * invB;
        Os[(c + 1) * 68 + rB] = o[t][3] * invB;
    }
    __syncthreads();

    const float gm = gamma[0];
    const int cc = tid >> 2, jj = tid & 3;
    #pragma unroll
    for (int cb = 0; cb < 4; cb++) {
        const int c = cb * 64 + cc;
        const size_t gbase = ((size_t)b * CC + c) * NN + m0 + jj * 16;
        #pragma unroll
        for (int v = 0; v < 4; v++) {
            float4 ov = *(float4*)&Os[c * 68 + jj * 16 + 4 * v];
            float4 xv = *(const float4*)&x[gbase + 4 * v];
            float4 rr;
            rr.x = gm * ov.x + xv.x;
            rr.y = gm * ov.y + xv.y;
            rr.z = gm * ov.z + xv.z;
            rr.w = gm * ov.w + xv.w;
            *(float4*)&out[gbase + 4 * v] = rr;
        }
    }
}

// ---------------------------------------------------------------------------
extern "C" void kernel_launch(void* const* d_in, const int* in_sizes, int n_in,
                              void* d_out, int out_size)
{
    (void)in_sizes; (void)n_in; (void)out_size;
    const float* x     = (const float*)d_in[0];
    const float* Wq    = (const float*)d_in[1];
    const float* bq    = (const float*)d_in[2];
    const float* Wk    = (const float*)d_in[3];
    const float* bk    = (const float*)d_in[4];
    const float* Wv    = (const float*)d_in[5];
    const float* bv    = (const float*)d_in[6];
    const float* rel_h = (const float*)d_in[7];
    const float* rel_w = (const float*)d_in[8];
    const float* gamma = (const float*)d_in[9];
    float* out = (float*)d_out;

    cudaFuncSetAttribute(attn_kernel,
                         cudaFuncAttributeMaxDynamicSharedMemorySize, SMEM_BYTES);

    proj_kernel<<<dim3(64, 4, 12), 256>>>(x, Wq, bq, Wk, bk, Wv, bv, rel_h, rel_w);
    attn_kernel<<<dim3(64, 4), 256, SMEM_BYTES>>>(x, gamma, out);
}

// round 14
// speedup vs baseline: 4.4703x; 1.0005x over previous
#include <cuda_runtime.h>
#include <cuda_bf16.h>
#include <stdint.h>
#include <math.h>

#define BB 4
#define CC 256
#define NN 4096

// bf16 hi/lo split operands
static __device__ __nv_bfloat16 g_Qh[BB*NN*CC], g_Ql[BB*NN*CC];   // token-major [b][n][c]
static __device__ __nv_bfloat16 g_Kh[BB*NN*CC], g_Kl[BB*NN*CC];   // token-major (pos folded)
static __device__ __nv_bfloat16 g_Vh[BB*NN*CC], g_Vl[BB*NN*CC];   // channel-major [b][c][n]

// ===================== helpers (base-target ISA only) =====================
__device__ __forceinline__ uint32_t smem_u32(const void* p) {
    uint32_t a;
    asm("{ .reg .u64 t; cvta.to.shared.u64 t, %1; cvt.u32.u64 %0, t; }" : "=r"(a) : "l"(p));
    return a;
}
__device__ __forceinline__ void ldsm4(uint32_t a, uint32_t r[4]) {
    asm volatile("ldmatrix.sync.aligned.m8n8.x4.shared.b16 {%0,%1,%2,%3}, [%4];"
        : "=r"(r[0]), "=r"(r[1]), "=r"(r[2]), "=r"(r[3]) : "r"(a));
}
__device__ __forceinline__ void mma16816(float d[4], const uint32_t a[4], uint32_t b0, uint32_t b1) {
    asm volatile("mma.sync.aligned.m16n8k16.row.col.f32.bf16.bf16.f32 "
        "{%0,%1,%2,%3}, {%4,%5,%6,%7}, {%8,%9}, {%0,%1,%2,%3};"
        : "+f"(d[0]), "+f"(d[1]), "+f"(d[2]), "+f"(d[3])
        : "r"(a[0]), "r"(a[1]), "r"(a[2]), "r"(a[3]), "r"(b0), "r"(b1));
}
__device__ __forceinline__ void cp16(uint32_t dst, const void* src) {
    asm volatile("cp.async.cg.shared.global [%0], [%1], 16;" :: "r"(dst), "l"(src));
}
#define CPC()  asm volatile("cp.async.commit_group;" ::: "memory")
#define CPW(n) asm volatile("cp.async.wait_group %0;" :: "n"(n) : "memory")
#define PAIRBAR(id) asm volatile("bar.sync %0, %1;" :: "r"(id), "r"(64) : "memory")

__device__ __forceinline__ uint32_t bfpack(__nv_bfloat16 a, __nv_bfloat16 b) {
    return (uint32_t)__bfloat16_as_ushort(a) | ((uint32_t)__bfloat16_as_ushort(b) << 16);
}

// smem byte offsets
#define QH_O 0
#define QL_O 33792
#define KH_O 67584
#define KL_O 101376
#define VH_O 135168
#define VL_O 172032
#define PH_O 208896
#define PL_O 218112
#define ST_O 227328
#define SMEM_BYTES 229376
// deltas
#define D_QL 33792
#define D_KL 33792
#define D_VL 36864
#define D_PL 9216

// ---------------------------------------------------------------------------
// Projection: out[b][n][o] = sum_c W[o][c] x[b][c][n] + bias (+pos for K)
// Emits bf16 hi/lo: Q,K token-major; V channel-major (smem transpose).
// ---------------------------------------------------------------------------
__global__ __launch_bounds__(256) void proj_kernel(
    const float* __restrict__ x,
    const float* __restrict__ Wq, const float* __restrict__ bq,
    const float* __restrict__ Wk, const float* __restrict__ bk,
    const float* __restrict__ Wv, const float* __restrict__ bv,
    const float* __restrict__ rel_h, const float* __restrict__ rel_w)
{
    __shared__ float Xs[16][64];
    __shared__ float Ws[16][68];
    __shared__ float Ts[64][65];

    const int tid = threadIdx.x;
    const int ty = tid >> 4, tx = tid & 15;
    const int n0 = blockIdx.x * 64;
    const int o0 = blockIdx.y * 64;
    const int b = blockIdx.z / 3;
    const int which = blockIdx.z % 3;

    const float* Wm   = (which == 0) ? Wq : (which == 1) ? Wk : Wv;
    const float* bias = (which == 0) ? bq : (which == 1) ? bk : bv;
    const float* xb = x + (size_t)b * CC * NN;

    const int lcl = tid >> 4, lnf = tid & 15;
    const int lo_ = tid >> 2, lcf = tid & 3;

    float acc[4][4] = {};
    for (int c0 = 0; c0 < CC; c0 += 16) {
        float4 xv = *(const float4*)&xb[(size_t)(c0 + lcl) * NN + n0 + lnf * 4];
        float4 wv = *(const float4*)&Wm[(o0 + lo_) * CC + c0 + lcf * 4];
        *(float4*)&Xs[lcl][lnf * 4] = xv;
        Ws[lcf * 4 + 0][lo_] = wv.x;
        Ws[lcf * 4 + 1][lo_] = wv.y;
        Ws[lcf * 4 + 2][lo_] = wv.z;
        Ws[lcf * 4 + 3][lo_] = wv.w;
        __syncthreads();
        #pragma unroll
        for (int kk = 0; kk < 16; kk++) {
            float4 a4 = *(const float4*)&Xs[kk][ty * 4];
            float4 w4 = *(const float4*)&Ws[kk][tx * 4];
            float a[4] = {a4.x, a4.y, a4.z, a4.w};
            float w[4] = {w4.x, w4.y, w4.z, w4.w};
            #pragma unroll
            for (int i = 0; i < 4; i++)
                #pragma unroll
                for (int j = 0; j < 4; j++)
                    acc[i][j] += a[i] * w[j];
        }
        __syncthreads();
    }

    float bs[4];
    #pragma unroll
    for (int j = 0; j < 4; j++) bs[j] = bias[o0 + tx * 4 + j];

    if (which < 2) {
        __nv_bfloat16* H = which ? g_Kh : g_Qh;
        __nv_bfloat16* L = which ? g_Kl : g_Ql;
        #pragma unroll
        for (int i = 0; i < 4; i++) {
            int n = n0 + ty * 4 + i;
            uint32_t hw[2], lw[2];
            #pragma unroll
            for (int jj = 0; jj < 2; jj++) {
                float r0 = acc[i][jj*2]   + bs[jj*2];
                float r1 = acc[i][jj*2+1] + bs[jj*2+1];
                if (which == 1) {
                    int c0 = o0 + tx * 4 + jj*2;
                    r0 += rel_h[c0 * 64 + (n >> 6)] + rel_w[c0 * 64 + (n & 63)];
                    r1 += rel_h[(c0+1) * 64 + (n >> 6)] + rel_w[(c0+1) * 64 + (n & 63)];
                }
                __nv_bfloat16 h0 = __float2bfloat16_rn(r0), h1 = __float2bfloat16_rn(r1);
                hw[jj] = bfpack(h0, h1);
                lw[jj] = bfpack(__float2bfloat16_rn(r0 - __bfloat162float(h0)),
                                __float2bfloat16_rn(r1 - __bfloat162float(h1)));
            }
            size_t gi = ((size_t)b * NN + n) * CC + o0 + tx * 4;
            *(uint2*)&H[gi] = make_uint2(hw[0], hw[1]);
            *(uint2*)&L[gi] = make_uint2(lw[0], lw[1]);
        }
    } else {
        // V: transpose to channel-major via smem
        #pragma unroll
        for (int i = 0; i < 4; i++)
            #pragma unroll
            for (int j = 0; j < 4; j++)
                Ts[tx * 4 + j][ty * 4 + i] = acc[i][j] + bs[j];
        __syncthreads();
        int cl = tid >> 2, n4 = tid & 3;
        uint32_t hw[8], lw[8];
        #pragma unroll
        for (int k = 0; k < 8; k++) {
            float v0 = Ts[cl][n4 * 16 + 2*k];
            float v1 = Ts[cl][n4 * 16 + 2*k + 1];
            __nv_bfloat16 h0 = __float2bfloat16_rn(v0), h1 = __float2bfloat16_rn(v1);
            hw[k] = bfpack(h0, h1);
            lw[k] = bfpack(__float2bfloat16_rn(v0 - __bfloat162float(h0)),
                           __float2bfloat16_rn(v1 - __bfloat162float(h1)));
        }
        size_t gi = ((size_t)b * CC + o0 + cl) * NN + n0 + n4 * 16;
        *(uint4*)&g_Vh[gi]     = make_uint4(hw[0], hw[1], hw[2], hw[3]);
        *(uint4*)&g_Vh[gi + 8] = make_uint4(hw[4], hw[5], hw[6], hw[7]);
        *(uint4*)&g_Vl[gi]     = make_uint4(lw[0], lw[1], lw[2], lw[3]);
        *(uint4*)&g_Vl[gi + 8] = make_uint4(lw[4], lw[5], lw[6], lw[7]);
    }
}

// ---------------------------------------------------------------------------
// HMMA flash attention, register-pipelined. grid (64, 4), 256 threads.
// Fragments double-buffered so LDSM overlaps MMA; softmax stats pair-scoped.
// ---------------------------------------------------------------------------
__global__ __launch_bounds__(256, 1) void attn_kernel(
    const float* __restrict__ x,
    const float* __restrict__ gamma,
    float* __restrict__ out)
{
    extern __shared__ char sm[];
    const uint32_t sb = smem_u32(sm);
    const int tid = threadIdx.x;
    const int wid = tid >> 5, ln = tid & 31;
    const int g = wid & 3, h = wid >> 2;
    const int b = blockIdx.y, m0 = blockIdx.x * 64;

    float* halfM = (float*)(sm + ST_O);          // [2][64]
    float* halfS = halfM + 128;                  // [2][64]

    const __nv_bfloat16* Qhg = g_Qh + ((size_t)b * NN + m0) * CC;
    const __nv_bfloat16* Qlg = g_Ql + ((size_t)b * NN + m0) * CC;

    auto loadK = [&](int nt) {
        const char* kh = (const char*)(g_Kh + ((size_t)b * NN + nt * 64) * CC);
        const char* kl = (const char*)(g_Kl + ((size_t)b * NN + nt * 64) * CC);
        for (int q = tid; q < 2048; q += 256) {
            int row = q >> 5, seg = q & 31;
            uint32_t d = sb + KH_O + row * 528 + seg * 16;
            cp16(d,        kh + row * 512 + seg * 16);
            cp16(d + D_KL, kl + row * 512 + seg * 16);
        }
    };
    auto loadV = [&](int nt) {
        const char* vh = (const char*)(g_Vh + (size_t)b * CC * NN + nt * 64);
        const char* vl = (const char*)(g_Vl + (size_t)b * CC * NN + nt * 64);
        for (int q = tid; q < 2048; q += 256) {
            int c = q >> 3, seg = q & 7;
            uint32_t d = sb + VH_O + c * 144 + seg * 16;
            cp16(d,        vh + (size_t)c * 8192 + seg * 16);
            cp16(d + D_VL, vl + (size_t)c * 8192 + seg * 16);
        }
    };

    // prologue: Q, K0, V0
    for (int q = tid; q < 2048; q += 256) {
        int row = q >> 5, seg = q & 31;
        uint32_t d = sb + QH_O + row * 528 + seg * 16;
        cp16(d,        (const char*)Qhg + row * 512 + seg * 16);
        cp16(d + D_QL, (const char*)Qlg + row * 512 + seg * 16);
    }
    CPC();
    loadK(0); CPC();
    loadV(0); CPC();

    // per-lane ldmatrix address components
    const uint32_t rowsel = ((ln >> 4) << 3) + (ln & 7);
    const uint32_t colsel = ((ln >> 3) & 1) << 4;
    const uint32_t asel   = (ln & 15);
    const uint32_t acol   = (ln >> 4) << 4;
    const uint32_t aQh = sb + QH_O + (16*g + asel) * 528 + acol;
    const uint32_t aQl = aQh + D_QL;
    const uint32_t bK0 = sb + KH_O + (32*h + rowsel) * 528 + colsel;
    const uint32_t bK1 = bK0 + 16 * 528;
    const uint32_t aPh = sb + PH_O + (16*g + asel) * 144 + acol;
    const uint32_t bV0 = sb + VH_O + (128*h + rowsel) * 144 + colsel;
    const int rA = 16*g + (ln >> 2), rB = rA + 8;

    float o[16][4];
    #pragma unroll
    for (int t = 0; t < 16; t++)
        #pragma unroll
        for (int j = 0; j < 4; j++) o[t][j] = 0.0f;
    float mA_base = 0.0f, mB_base = 0.0f, lA = 0.0f, lB = 0.0f;

    for (int nt = 0; nt < 64; nt++) {
        CPW(1);            // K(nt) (and Q) resident; V(nt) may still be in flight
        __syncthreads();

        // ---- QK: S(64x64), pipelined fragments ----
        uint32_t ah[2][4], al[2][4], bh0[2][4], bh1[2][4];
        ldsm4(aQh, ah[0]); ldsm4(aQl, al[0]);
        ldsm4(bK0, bh0[0]); ldsm4(bK1, bh1[0]);
        float s0[4] = {}, s1[4] = {}, s2[4] = {}, s3[4] = {};
        #pragma unroll
        for (int kk = 0; kk < 16; kk++) {
            const int cur = kk & 1, nxt = cur ^ 1;
            const uint32_t ko = kk * 32;
            uint32_t bl0[4], bl1[4];
            ldsm4(bK0 + D_KL + ko, bl0); ldsm4(bK1 + D_KL + ko, bl1);
            if (kk < 15) {
                ldsm4(aQh + ko + 32, ah[nxt]);  ldsm4(aQl + ko + 32, al[nxt]);
                ldsm4(bK0 + ko + 32, bh0[nxt]); ldsm4(bK1 + ko + 32, bh1[nxt]);
            }
            mma16816(s0, ah[cur], bh0[cur][0], bh0[cur][1]);
            mma16816(s1, ah[cur], bh0[cur][2], bh0[cur][3]);
            mma16816(s2, ah[cur], bh1[cur][0], bh1[cur][1]);
            mma16816(s3, ah[cur], bh1[cur][2], bh1[cur][3]);
            mma16816(s0, al[cur], bh0[cur][0], bh0[cur][1]);
            mma16816(s1, al[cur], bh0[cur][2], bh0[cur][3]);
            mma16816(s2, al[cur], bh1[cur][0], bh1[cur][1]);
            mma16816(s3, al[cur], bh1[cur][2], bh1[cur][3]);
            mma16816(s0, ah[cur], bl0[0], bl0[1]);
            mma16816(s1, ah[cur], bl0[2], bl0[3]);
            mma16816(s2, ah[cur], bl1[0], bl1[1]);
            mma16816(s3, ah[cur], bl1[2], bl1[3]);
        }
        __syncthreads();               // everyone done reading K
        if (nt < 63) loadK(nt + 1);
        CPC();

        // ---- softmax: stats pair-scoped (warps g and g+4 only) ----
        float mAl = fmaxf(fmaxf(s0[0], s0[1]), fmaxf(s1[0], s1[1]));
        mAl = fmaxf(mAl, fmaxf(fmaxf(s2[0], s2[1]), fmaxf(s3[0], s3[1])));
        float mBl = fmaxf(fmaxf(s0[2], s0[3]), fmaxf(s1[2], s1[3]));
        mBl = fmaxf(mBl, fmaxf(fmaxf(s2[2], s2[3]), fmaxf(s3[2], s3[3])));
        mAl = fmaxf(mAl, __shfl_xor_sync(0xffffffffu, mAl, 1));
        mAl = fmaxf(mAl, __shfl_xor_sync(0xffffffffu, mAl, 2));
        mBl = fmaxf(mBl, __shfl_xor_sync(0xffffffffu, mBl, 1));
        mBl = fmaxf(mBl, __shfl_xor_sync(0xffffffffu, mBl, 2));
        if ((ln & 3) == 0) { halfM[h*64 + rA] = mAl; halfM[h*64 + rB] = mBl; }
        PAIRBAR(1 + g);
        float tmA = fmaxf(halfM[rA], halfM[64 + rA]);
        float tmB = fmaxf(halfM[rB], halfM[64 + rB]);
        float fA = 1.0f, fB = 1.0f;
        if (nt == 0) {
            mA_base = tmA; mB_base = tmB;
        } else {
            if (tmA > mA_base + 25.0f) { fA = __expf(mA_base - tmA); mA_base = tmA; }
            if (tmB > mB_base + 25.0f) { fB = __expf(mB_base - tmB); mB_base = tmB; }
        }

        float pA = 0.0f, pB = 0.0f;
        {
            const uint32_t cbyte = (32*h + 2*(ln & 3)) * 2;
            char* baA = sm + PH_O + rA * 144 + cbyte;
            char* baB = sm + PH_O + rB * 144 + cbyte;
            float* sv[4] = {s0, s1, s2, s3};
            #pragma unroll
            for (int t = 0; t < 4; t++) {
                float p0 = __expf(sv[t][0] - mA_base);
                float p1 = __expf(sv[t][1] - mA_base);
                float p2 = __expf(sv[t][2] - mB_base);
                float p3 = __expf(sv[t][3] - mB_base);
                pA += p0 + p1; pB += p2 + p3;
                __nv_bfloat16 h0 = __float2bfloat16_rn(p0), h1 = __float2bfloat16_rn(p1);
                __nv_bfloat16 h2 = __float2bfloat16_rn(p2), h3 = __float2bfloat16_rn(p3);
                *(uint32_t*)(baA + t*16)        = bfpack(h0, h1);
                *(uint32_t*)(baB + t*16)        = bfpack(h2, h3);
                *(uint32_t*)(baA + D_PL + t*16) = bfpack(__float2bfloat16_rn(p0 - __bfloat162float(h0)),
                                                         __float2bfloat16_rn(p1 - __bfloat162float(h1)));
                *(uint32_t*)(baB + D_PL + t*16) = bfpack(__float2bfloat16_rn(p2 - __bfloat162float(h2)),
                                                         __float2bfloat16_rn(p3 - __bfloat162float(h3)));
            }
        }
        pA += __shfl_xor_sync(0xffffffffu, pA, 1);
        pA += __shfl_xor_sync(0xffffffffu, pA, 2);
        pB += __shfl_xor_sync(0xffffffffu, pB, 1);
        pB += __shfl_xor_sync(0xffffffffu, pB, 2);
        if ((ln & 3) == 0) { halfS[h*64 + rA] = pA; halfS[h*64 + rB] = pB; }
        PAIRBAR(1 + g);
        lA = lA * fA + halfS[rA] + halfS[64 + rA];
        lB = lB * fB + halfS[rB] + halfS[64 + rB];

        CPW(1);            // V(nt) resident; K(nt+1) may be in flight
        __syncthreads();

        // ---- O lazy rescale (rare) ----
        if (__ballot_sync(0xffffffffu, (fA != 1.0f) || (fB != 1.0f))) {
            #pragma unroll
            for (int t = 0; t < 16; t++) {
                o[t][0] *= fA; o[t][1] *= fA; o[t][2] *= fB; o[t][3] *= fB;
            }
        }

        // ---- PV: O += P @ V, pipelined fragments (32 flat iterations) ----
        uint32_t ph[2][4], pl[2][4], vh[2][4], vl[2][4];
        ldsm4(aPh, ph[0]); ldsm4(aPh + D_PL, pl[0]);
        ldsm4(bV0, vh[0]); ldsm4(bV0 + D_VL, vl[0]);
        #pragma unroll
        for (int i = 0; i < 32; i++) {
            const int t = i & 7, kk = i >> 3;
            const int vc = i & 1, vn = vc ^ 1;
            const int pc = kk & 1;
            if (i < 31) {
                const uint32_t nvb = bV0 + (uint32_t)((i+1) & 7) * (16*144) + (uint32_t)((i+1) >> 3) * 32;
                ldsm4(nvb, vh[vn]); ldsm4(nvb + D_VL, vl[vn]);
                if (((i + 1) & 7) == 0) {
                    const uint32_t npo = (uint32_t)((i+1) >> 3) * 32;
                    ldsm4(aPh + npo, ph[pc ^ 1]); ldsm4(aPh + D_PL + npo, pl[pc ^ 1]);
                }
            }
            mma16816(o[2*t],   ph[pc], vh[vc][0], vh[vc][1]);
            mma16816(o[2*t+1], ph[pc], vh[vc][2], vh[vc][3]);
            mma16816(o[2*t],   ph[pc], vl[vc][0], vl[vc][1]);
            mma16816(o[2*t+1], ph[pc], vl[vc][2], vl[vc][3]);
            mma16816(o[2*t],   pl[pc], vh[vc][0], vh[vc][1]);
            mma16816(o[2*t+1], pl[pc], vh[vc][2], vh[vc][3]);
        }
        __syncthreads();               // done reading V & P
        if (nt < 63) loadV(nt + 1);
        CPC();
    }

    // ---- epilogue: O/l, transpose through (free) V region, residual ----
    __syncthreads();
    const float invA = 1.0f / lA;
    const float invB = 1.0f / lB;
    float* Os = (float*)(sm + VH_O);   // [256 c][68 tok]
    #pragma unroll
    for (int t = 0; t < 16; t++) {
        int c = 128*h + 16*(t >> 1) + 8*(t & 1) + 2*(ln & 3);
        Os[c * 68 + rA]       = o[t][0] * invA;
        Os[(c + 1) * 68 + rA] = o[t][1] * invA;
        Os[c * 68 + rB]       = o[t][2] * invB;
        Os[(c + 1) * 68 + rB] = o[t][3] * invB;
    }
    __syncthreads();

    const float gm = gamma[0];
    const int cc = tid >> 2, jj = tid & 3;
    #pragma unroll
    for (int cb = 0; cb < 4; cb++) {
        const int c = cb * 64 + cc;
        const size_t gbase = ((size_t)b * CC + c) * NN + m0 + jj * 16;
        #pragma unroll
        for (int v = 0; v < 4; v++) {
            float4 ov = *(float4*)&Os[c * 68 + jj * 16 + 4 * v];
            float4 xv = *(const float4*)&x[gbase + 4 * v];
            float4 rr;
            rr.x = gm * ov.x + xv.x;
            rr.y = gm * ov.y + xv.y;
            rr.z = gm * ov.z + xv.z;
            rr.w = gm * ov.w + xv.w;
            *(float4*)&out[gbase + 4 * v] = rr;
        }
    }
}

// ---------------------------------------------------------------------------
extern "C" void kernel_launch(void* const* d_in, const int* in_sizes, int n_in,
                              void* d_out, int out_size)
{
    (void)in_sizes; (void)n_in; (void)out_size;
    const float* x     = (const float*)d_in[0];
    const float* Wq    = (const float*)d_in[1];
    const float* bq    = (const float*)d_in[2];
    const float* Wk    = (const float*)d_in[3];
    const float* bk    = (const float*)d_in[4];
    const float* Wv    = (const float*)d_in[5];
    const float* bv    = (const float*)d_in[6];
    const float* rel_h = (const float*)d_in[7];
    const float* rel_w = (const float*)d_in[8];
    const float* gamma = (const float*)d_in[9];
    float* out = (float*)d_out;

    cudaFuncSetAttribute(attn_kernel,
                         cudaFuncAttributeMaxDynamicSharedMemorySize, SMEM_BYTES);

    proj_kernel<<<dim3(64, 4, 12), 256>>>(x, Wq, bq, Wk, bk, Wv, bv, rel_h, rel_w);
    attn_kernel<<<dim3(64, 4), 256, SMEM_BYTES>>>(x, gamma, out);
}

// round 15
// speedup vs baseline: 4.5845x; 1.0255x over previous
#include <cuda_runtime.h>
#include <cuda_bf16.h>
#include <stdint.h>
#include <math.h>

#define BB 4
#define CC 256
#define NN 4096

// bf16 hi/lo split operands
static __device__ __nv_bfloat16 g_Qh[BB*NN*CC], g_Ql[BB*NN*CC];   // token-major [b][n][c]
static __device__ __nv_bfloat16 g_Kh[BB*NN*CC], g_Kl[BB*NN*CC];   // token-major (pos folded)
static __device__ __nv_bfloat16 g_Vh[BB*NN*CC], g_Vl[BB*NN*CC];   // channel-major [b][c][n]

// ===================== helpers (base-target ISA only) =====================
__device__ __forceinline__ uint32_t smem_u32(const void* p) {
    uint32_t a;
    asm("{ .reg .u64 t; cvta.to.shared.u64 t, %1; cvt.u32.u64 %0, t; }" : "=r"(a) : "l"(p));
    return a;
}
__device__ __forceinline__ void ldsm4(uint32_t a, uint32_t r[4]) {
    asm volatile("ldmatrix.sync.aligned.m8n8.x4.shared.b16 {%0,%1,%2,%3}, [%4];"
        : "=r"(r[0]), "=r"(r[1]), "=r"(r[2]), "=r"(r[3]) : "r"(a));
}
__device__ __forceinline__ void mma16816(float d[4], const uint32_t a[4], uint32_t b0, uint32_t b1) {
    asm volatile("mma.sync.aligned.m16n8k16.row.col.f32.bf16.bf16.f32 "
        "{%0,%1,%2,%3}, {%4,%5,%6,%7}, {%8,%9}, {%0,%1,%2,%3};"
        : "+f"(d[0]), "+f"(d[1]), "+f"(d[2]), "+f"(d[3])
        : "r"(a[0]), "r"(a[1]), "r"(a[2]), "r"(a[3]), "r"(b0), "r"(b1));
}
__device__ __forceinline__ void cp16(uint32_t dst, const void* src) {
    asm volatile("cp.async.cg.shared.global [%0], [%1], 16;" :: "r"(dst), "l"(src));
}
#define CPC()  asm volatile("cp.async.commit_group;" ::: "memory")
#define CPW(n) asm volatile("cp.async.wait_group %0;" :: "n"(n) : "memory")
#define PAIRBAR(id) asm volatile("bar.sync %0, %1;" :: "r"(id), "r"(64) : "memory")

__device__ __forceinline__ uint32_t bfpack(__nv_bfloat16 a, __nv_bfloat16 b) {
    return (uint32_t)__bfloat16_as_ushort(a) | ((uint32_t)__bfloat16_as_ushort(b) << 16);
}

// smem byte offsets
#define QH_O 0
#define QL_O 33792
#define KH_O 67584
#define KL_O 101376
#define VH_O 135168
#define VL_O 172032
#define ST_O 208896
#define SMEM_BYTES 209920
// deltas
#define D_QL 33792
#define D_KL 33792
#define D_VL 36864

// ---------------------------------------------------------------------------
// Projection: out[b][n][o] = sum_c W[o][c] x[b][c][n] + bias (+pos for K)
// Emits bf16 hi/lo: Q,K token-major; V channel-major (smem transpose).
// ---------------------------------------------------------------------------
__global__ __launch_bounds__(256) void proj_kernel(
    const float* __restrict__ x,
    const float* __restrict__ Wq, const float* __restrict__ bq,
    const float* __restrict__ Wk, const float* __restrict__ bk,
    const float* __restrict__ Wv, const float* __restrict__ bv,
    const float* __restrict__ rel_h, const float* __restrict__ rel_w)
{
    __shared__ float Xs[16][64];
    __shared__ float Ws[16][68];
    __shared__ float Ts[64][65];

    const int tid = threadIdx.x;
    const int ty = tid >> 4, tx = tid & 15;
    const int n0 = blockIdx.x * 64;
    const int o0 = blockIdx.y * 64;
    const int b = blockIdx.z / 3;
    const int which = blockIdx.z % 3;

    const float* Wm   = (which == 0) ? Wq : (which == 1) ? Wk : Wv;
    const float* bias = (which == 0) ? bq : (which == 1) ? bk : bv;
    const float* xb = x + (size_t)b * CC * NN;

    const int lcl = tid >> 4, lnf = tid & 15;
    const int lo_ = tid >> 2, lcf = tid & 3;

    float acc[4][4] = {};
    for (int c0 = 0; c0 < CC; c0 += 16) {
        float4 xv = *(const float4*)&xb[(size_t)(c0 + lcl) * NN + n0 + lnf * 4];
        float4 wv = *(const float4*)&Wm[(o0 + lo_) * CC + c0 + lcf * 4];
        *(float4*)&Xs[lcl][lnf * 4] = xv;
        Ws[lcf * 4 + 0][lo_] = wv.x;
        Ws[lcf * 4 + 1][lo_] = wv.y;
        Ws[lcf * 4 + 2][lo_] = wv.z;
        Ws[lcf * 4 + 3][lo_] = wv.w;
        __syncthreads();
        #pragma unroll
        for (int kk = 0; kk < 16; kk++) {
            float4 a4 = *(const float4*)&Xs[kk][ty * 4];
            float4 w4 = *(const float4*)&Ws[kk][tx * 4];
            float a[4] = {a4.x, a4.y, a4.z, a4.w};
            float w[4] = {w4.x, w4.y, w4.z, w4.w};
            #pragma unroll
            for (int i = 0; i < 4; i++)
                #pragma unroll
                for (int j = 0; j < 4; j++)
                    acc[i][j] += a[i] * w[j];
        }
        __syncthreads();
    }

    float bs[4];
    #pragma unroll
    for (int j = 0; j < 4; j++) bs[j] = bias[o0 + tx * 4 + j];

    if (which < 2) {
        __nv_bfloat16* H = which ? g_Kh : g_Qh;
        __nv_bfloat16* L = which ? g_Kl : g_Ql;
        #pragma unroll
        for (int i = 0; i < 4; i++) {
            int n = n0 + ty * 4 + i;
            uint32_t hw[2], lw[2];
            #pragma unroll
            for (int jj = 0; jj < 2; jj++) {
                float r0 = acc[i][jj*2]   + bs[jj*2];
                float r1 = acc[i][jj*2+1] + bs[jj*2+1];
                if (which == 1) {
                    int c0 = o0 + tx * 4 + jj*2;
                    r0 += rel_h[c0 * 64 + (n >> 6)] + rel_w[c0 * 64 + (n & 63)];
                    r1 += rel_h[(c0+1) * 64 + (n >> 6)] + rel_w[(c0+1) * 64 + (n & 63)];
                }
                __nv_bfloat16 h0 = __float2bfloat16_rn(r0), h1 = __float2bfloat16_rn(r1);
                hw[jj] = bfpack(h0, h1);
                lw[jj] = bfpack(__float2bfloat16_rn(r0 - __bfloat162float(h0)),
                                __float2bfloat16_rn(r1 - __bfloat162float(h1)));
            }
            size_t gi = ((size_t)b * NN + n) * CC + o0 + tx * 4;
            *(uint2*)&H[gi] = make_uint2(hw[0], hw[1]);
            *(uint2*)&L[gi] = make_uint2(lw[0], lw[1]);
        }
    } else {
        // V: transpose to channel-major via smem
        #pragma unroll
        for (int i = 0; i < 4; i++)
            #pragma unroll
            for (int j = 0; j < 4; j++)
                Ts[tx * 4 + j][ty * 4 + i] = acc[i][j] + bs[j];
        __syncthreads();
        int cl = tid >> 2, n4 = tid & 3;
        uint32_t hw[8], lw[8];
        #pragma unroll
        for (int k = 0; k < 8; k++) {
            float v0 = Ts[cl][n4 * 16 + 2*k];
            float v1 = Ts[cl][n4 * 16 + 2*k + 1];
            __nv_bfloat16 h0 = __float2bfloat16_rn(v0), h1 = __float2bfloat16_rn(v1);
            hw[k] = bfpack(h0, h1);
            lw[k] = bfpack(__float2bfloat16_rn(v0 - __bfloat162float(h0)),
                           __float2bfloat16_rn(v1 - __bfloat162float(h1)));
        }
        size_t gi = ((size_t)b * CC + o0 + cl) * NN + n0 + n4 * 16;
        *(uint4*)&g_Vh[gi]     = make_uint4(hw[0], hw[1], hw[2], hw[3]);
        *(uint4*)&g_Vh[gi + 8] = make_uint4(hw[4], hw[5], hw[6], hw[7]);
        *(uint4*)&g_Vl[gi]     = make_uint4(lw[0], lw[1], lw[2], lw[3]);
        *(uint4*)&g_Vl[gi + 8] = make_uint4(lw[4], lw[5], lw[6], lw[7]);
    }
}

// ---------------------------------------------------------------------------
// HMMA flash attention, P kept in registers (S c-frag == PV A-frag layout).
// Each warp: 16 queries x its 32 keys x ALL 256 channels (partial O).
// Key-halves summed in epilogue. grid (64, 4), 256 threads.
// ---------------------------------------------------------------------------
__global__ __launch_bounds__(256, 1) void attn_kernel(
    const float* __restrict__ x,
    const float* __restrict__ gamma,
    float* __restrict__ out)
{
    extern __shared__ char sm[];
    const uint32_t sb = smem_u32(sm);
    const int tid = threadIdx.x;
    const int wid = tid >> 5, ln = tid & 31;
    const int g = wid & 3, h = wid >> 2;
    const int b = blockIdx.y, m0 = blockIdx.x * 64;

    float* halfM = (float*)(sm + ST_O);          // [2][64]
    float* halfS = halfM + 128;                  // [2][64]

    const __nv_bfloat16* Qhg = g_Qh + ((size_t)b * NN + m0) * CC;
    const __nv_bfloat16* Qlg = g_Ql + ((size_t)b * NN + m0) * CC;

    auto loadK = [&](int nt) {
        const char* kh = (const char*)(g_Kh + ((size_t)b * NN + nt * 64) * CC);
        const char* kl = (const char*)(g_Kl + ((size_t)b * NN + nt * 64) * CC);
        for (int q = tid; q < 2048; q += 256) {
            int row = q >> 5, seg = q & 31;
            uint32_t d = sb + KH_O + row * 528 + seg * 16;
            cp16(d,        kh + row * 512 + seg * 16);
            cp16(d + D_KL, kl + row * 512 + seg * 16);
        }
    };
    auto loadV = [&](int nt) {
        const char* vh = (const char*)(g_Vh + (size_t)b * CC * NN + nt * 64);
        const char* vl = (const char*)(g_Vl + (size_t)b * CC * NN + nt * 64);
        for (int q = tid; q < 2048; q += 256) {
            int c = q >> 3, seg = q & 7;
            uint32_t d = sb + VH_O + c * 144 + seg * 16;
            cp16(d,        vh + (size_t)c * 8192 + seg * 16);
            cp16(d + D_VL, vl + (size_t)c * 8192 + seg * 16);
        }
    };

    // prologue: Q, K0, V0
    for (int q = tid; q < 2048; q += 256) {
        int row = q >> 5, seg = q & 31;
        uint32_t d = sb + QH_O + row * 528 + seg * 16;
        cp16(d,        (const char*)Qhg + row * 512 + seg * 16);
        cp16(d + D_QL, (const char*)Qlg + row * 512 + seg * 16);
    }
    CPC();
    loadK(0); CPC();
    loadV(0); CPC();

    // per-lane ldmatrix address components
    const uint32_t rowsel = ((ln >> 4) << 3) + (ln & 7);
    const uint32_t colsel = ((ln >> 3) & 1) << 4;
    const uint32_t asel   = (ln & 15);
    const uint32_t acol   = (ln >> 4) << 4;
    const uint32_t aQh = sb + QH_O + (16*g + asel) * 528 + acol;
    const uint32_t aQl = aQh + D_QL;
    const uint32_t bK0 = sb + KH_O + (32*h + rowsel) * 528 + colsel;
    const uint32_t bK1 = bK0 + 16 * 528;
    // V: rows = channels, cols = keys; this warp's 32 keys start at byte 64*h
    const uint32_t bV  = sb + VH_O + rowsel * 144 + colsel + 64u * h;
    const int rA = 16*g + (ln >> 2), rB = rA + 8;

    float o[32][4];
    #pragma unroll
    for (int t = 0; t < 32; t++)
        #pragma unroll
        for (int j = 0; j < 4; j++) o[t][j] = 0.0f;
    float mA_base = 0.0f, mB_base = 0.0f, lA = 0.0f, lB = 0.0f;

    for (int nt = 0; nt < 64; nt++) {
        CPW(1);            // K(nt) resident; V(nt) may still be in flight
        __syncthreads();

        // ---- QK: S(64x64), 3-way split ----
        float s[4][4];
        #pragma unroll
        for (int t = 0; t < 4; t++)
            #pragma unroll
            for (int j = 0; j < 4; j++) s[t][j] = 0.0f;
        #pragma unroll
        for (int kk = 0; kk < 16; kk++) {
            uint32_t ah[4], al[4], bh0[4], bh1[4], bl0[4], bl1[4];
            const uint32_t ko = kk * 32;
            ldsm4(aQh + ko, ah); ldsm4(aQl + ko, al);
            ldsm4(bK0 + ko, bh0); ldsm4(bK1 + ko, bh1);
            ldsm4(bK0 + D_KL + ko, bl0); ldsm4(bK1 + D_KL + ko, bl1);
            mma16816(s[0], ah, bh0[0], bh0[1]); mma16816(s[1], ah, bh0[2], bh0[3]);
            mma16816(s[2], ah, bh1[0], bh1[1]); mma16816(s[3], ah, bh1[2], bh1[3]);
            mma16816(s[0], ah, bl0[0], bl0[1]); mma16816(s[1], ah, bl0[2], bl0[3]);
            mma16816(s[2], ah, bl1[0], bl1[1]); mma16816(s[3], ah, bl1[2], bl1[3]);
            mma16816(s[0], al, bh0[0], bh0[1]); mma16816(s[1], al, bh0[2], bh0[3]);
            mma16816(s[2], al, bh1[0], bh1[1]); mma16816(s[3], al, bh1[2], bh1[3]);
        }
        CPW(0);                        // V(nt) done too (visibility via next barrier)
        __syncthreads();               // everyone done reading K; V visible to all
        if (nt < 63) loadK(nt + 1);
        CPC();

        // ---- softmax: stats pair-scoped; P stays in registers ----
        float mAl = fmaxf(fmaxf(s[0][0], s[0][1]), fmaxf(s[1][0], s[1][1]));
        mAl = fmaxf(mAl, fmaxf(fmaxf(s[2][0], s[2][1]), fmaxf(s[3][0], s[3][1])));
        float mBl = fmaxf(fmaxf(s[0][2], s[0][3]), fmaxf(s[1][2], s[1][3]));
        mBl = fmaxf(mBl, fmaxf(fmaxf(s[2][2], s[2][3]), fmaxf(s[3][2], s[3][3])));
        mAl = fmaxf(mAl, __shfl_xor_sync(0xffffffffu, mAl, 1));
        mAl = fmaxf(mAl, __shfl_xor_sync(0xffffffffu, mAl, 2));
        mBl = fmaxf(mBl, __shfl_xor_sync(0xffffffffu, mBl, 1));
        mBl = fmaxf(mBl, __shfl_xor_sync(0xffffffffu, mBl, 2));
        if ((ln & 3) == 0) { halfM[h*64 + rA] = mAl; halfM[h*64 + rB] = mBl; }
        PAIRBAR(1 + g);
        float tmA = fmaxf(halfM[rA], halfM[64 + rA]);
        float tmB = fmaxf(halfM[rB], halfM[64 + rB]);
        float fA = 1.0f, fB = 1.0f;
        if (nt == 0) {
            mA_base = tmA; mB_base = tmB;
        } else {
            if (tmA > mA_base + 25.0f) { fA = __expf(mA_base - tmA); mA_base = tmA; }
            if (tmB > mB_base + 25.0f) { fB = __expf(mB_base - tmB); mB_base = tmB; }
        }

        uint32_t ph[2][4], pl[2][4];
        float pA = 0.0f, pB = 0.0f;
        #pragma unroll
        for (int t = 0; t < 4; t++) {
            float p0 = __expf(s[t][0] - mA_base);
            float p1 = __expf(s[t][1] - mA_base);
            float p2 = __expf(s[t][2] - mB_base);
            float p3 = __expf(s[t][3] - mB_base);
            pA += p0 + p1; pB += p2 + p3;
            __nv_bfloat16 h0 = __float2bfloat16_rn(p0), h1 = __float2bfloat16_rn(p1);
            __nv_bfloat16 h2 = __float2bfloat16_rn(p2), h3 = __float2bfloat16_rn(p3);
            const int ck = t >> 1, ps = (t & 1) << 1;
            ph[ck][ps]     = bfpack(h0, h1);
            ph[ck][ps + 1] = bfpack(h2, h3);
            pl[ck][ps]     = bfpack(__float2bfloat16_rn(p0 - __bfloat162float(h0)),
                                    __float2bfloat16_rn(p1 - __bfloat162float(h1)));
            pl[ck][ps + 1] = bfpack(__float2bfloat16_rn(p2 - __bfloat162float(h2)),
                                    __float2bfloat16_rn(p3 - __bfloat162float(h3)));
        }
        pA += __shfl_xor_sync(0xffffffffu, pA, 1);
        pA += __shfl_xor_sync(0xffffffffu, pA, 2);
        pB += __shfl_xor_sync(0xffffffffu, pB, 1);
        pB += __shfl_xor_sync(0xffffffffu, pB, 2);
        if ((ln & 3) == 0) { halfS[h*64 + rA] = pA; halfS[h*64 + rB] = pB; }
        PAIRBAR(1 + g);
        lA = lA * fA + halfS[rA] + halfS[64 + rA];
        lB = lB * fB + halfS[rB] + halfS[64 + rB];

        // ---- O lazy rescale (rare) ----
        if (__ballot_sync(0xffffffffu, (fA != 1.0f) || (fB != 1.0f))) {
            #pragma unroll
            for (int t = 0; t < 32; t++) {
                o[t][0] *= fA; o[t][1] *= fA; o[t][2] *= fB; o[t][3] *= fB;
            }
        }

        // ---- PV: partial O over this warp's 32 keys, all 256 channels ----
        uint32_t vh[2][4], vl[2][4];
        ldsm4(bV, vh[0]); ldsm4(bV + D_VL, vl[0]);
        #pragma unroll
        for (int i = 0; i < 32; i++) {
            const int tt = i >> 1, ck = i & 1;
            const int cur = i & 1, nxt = cur ^ 1;
            if (i < 31) {
                const uint32_t nb = bV + (uint32_t)((i+1) >> 1) * (16*144)
                                       + (uint32_t)((i+1) & 1) * 32;
                ldsm4(nb, vh[nxt]); ldsm4(nb + D_VL, vl[nxt]);
            }
            mma16816(o[2*tt],   ph[ck], vh[cur][0], vh[cur][1]);
            mma16816(o[2*tt+1], ph[ck], vh[cur][2], vh[cur][3]);
            mma16816(o[2*tt],   ph[ck], vl[cur][0], vl[cur][1]);
            mma16816(o[2*tt+1], ph[ck], vl[cur][2], vl[cur][3]);
            mma16816(o[2*tt],   pl[ck], vh[cur][0], vh[cur][1]);
            mma16816(o[2*tt+1], pl[ck], vh[cur][2], vh[cur][3]);
        }
        __syncthreads();               // all warps done reading V(nt)
        if (nt < 63) loadV(nt + 1);
        CPC();
    }

    // ---- epilogue: sum key-halves into Os, apply 1/l, residual store ----
    __syncthreads();
    const float invA = 1.0f / lA;
    const float invB = 1.0f / lB;
    float* Os = (float*)(sm + VH_O);   // [256 c][68 tok]
    if (h == 0) {
        #pragma unroll
        for (int t = 0; t < 32; t++) {
            const int c0 = 8*t + 2*(ln & 3);
            Os[c0 * 68 + rA]       = o[t][0] * invA;
            Os[(c0 + 1) * 68 + rA] = o[t][1] * invA;
            Os[c0 * 68 + rB]       = o[t][2] * invB;
            Os[(c0 + 1) * 68 + rB] = o[t][3] * invB;
        }
    }
    __syncthreads();
    if (h == 1) {
        #pragma unroll
        for (int t = 0; t < 32; t++) {
            const int c0 = 8*t + 2*(ln & 3);
            Os[c0 * 68 + rA]       += o[t][0] * invA;
            Os[(c0 + 1) * 68 + rA] += o[t][1] * invA;
            Os[c0 * 68 + rB]       += o[t][2] * invB;
            Os[(c0 + 1) * 68 + rB] += o[t][3] * invB;
        }
    }
    __syncthreads();

    const float gm = gamma[0];
    const int cc = tid >> 2, jj = tid & 3;
    #pragma unroll
    for (int cb = 0; cb < 4; cb++) {
        const int c = cb * 64 + cc;
        const size_t gbase = ((size_t)b * CC + c) * NN + m0 + jj * 16;
        #pragma unroll
        for (int v = 0; v < 4; v++) {
            float4 ov = *(float4*)&Os[c * 68 + jj * 16 + 4 * v];
            float4 xv = *(const float4*)&x[gbase + 4 * v];
            float4 rr;
            rr.x = gm * ov.x + xv.x;
            rr.y = gm * ov.y + xv.y;
            rr.z = gm * ov.z + xv.z;
            rr.w = gm * ov.w + xv.w;
            *(float4*)&out[gbase + 4 * v] = rr;
        }
    }
}

// ---------------------------------------------------------------------------
extern "C" void kernel_launch(void* const* d_in, const int* in_sizes, int n_in,
                              void* d_out, int out_size)
{
    (void)in_sizes; (void)n_in; (void)out_size;
    const float* x     = (const float*)d_in[0];
    const float* Wq    = (const float*)d_in[1];
    const float* bq    = (const float*)d_in[2];
    const float* Wk    = (const float*)d_in[3];
    const float* bk    = (const float*)d_in[4];
    const float* Wv    = (const float*)d_in[5];
    const float* bv    = (const float*)d_in[6];
    const float* rel_h = (const float*)d_in[7];
    const float* rel_w = (const float*)d_in[8];
    const float* gamma = (const float*)d_in[9];
    float* out = (float*)d_out;

    cudaFuncSetAttribute(attn_kernel,
                         cudaFuncAttributeMaxDynamicSharedMemorySize, SMEM_BYTES);

    proj_kernel<<<dim3(64, 4, 12), 256>>>(x, Wq, bq, Wk, bk, Wv, bv, rel_h, rel_w);
    attn_kernel<<<dim3(64, 4), 256, SMEM_BYTES>>>(x, gamma, out);
}

// round 17
// speedup vs baseline: 5.7474x; 1.2537x over previous
#include <cuda_runtime.h>
#include <cuda_bf16.h>
#include <cuda_fp16.h>
#include <stdint.h>
#include <math.h>

#define BB 4
#define CC 256
#define NN 4096

// Q/K: bf16 hi/lo split (token-major). V: single fp16 (channel-major).
static __device__ __nv_bfloat16 g_Qh[BB*NN*CC], g_Ql[BB*NN*CC];
static __device__ __nv_bfloat16 g_Kh[BB*NN*CC], g_Kl[BB*NN*CC];
static __device__ __half        g_V [BB*NN*CC];

// ===================== helpers (base-target ISA only) =====================
__device__ __forceinline__ uint32_t smem_u32(const void* p) {
    uint32_t a;
    asm("{ .reg .u64 t; cvta.to.shared.u64 t, %1; cvt.u32.u64 %0, t; }" : "=r"(a) : "l"(p));
    return a;
}
__device__ __forceinline__ void ldsm4(uint32_t a, uint32_t r[4]) {
    asm volatile("ldmatrix.sync.aligned.m8n8.x4.shared.b16 {%0,%1,%2,%3}, [%4];"
        : "=r"(r[0]), "=r"(r[1]), "=r"(r[2]), "=r"(r[3]) : "r"(a));
}
__device__ __forceinline__ void mma16816(float d[4], const uint32_t a[4], uint32_t b0, uint32_t b1) {
    asm volatile("mma.sync.aligned.m16n8k16.row.col.f32.bf16.bf16.f32 "
        "{%0,%1,%2,%3}, {%4,%5,%6,%7}, {%8,%9}, {%0,%1,%2,%3};"
        : "+f"(d[0]), "+f"(d[1]), "+f"(d[2]), "+f"(d[3])
        : "r"(a[0]), "r"(a[1]), "r"(a[2]), "r"(a[3]), "r"(b0), "r"(b1));
}
__device__ __forceinline__ void mma16816h(float d[4], const uint32_t a[4], uint32_t b0, uint32_t b1) {
    asm volatile("mma.sync.aligned.m16n8k16.row.col.f32.f16.f16.f32 "
        "{%0,%1,%2,%3}, {%4,%5,%6,%7}, {%8,%9}, {%0,%1,%2,%3};"
        : "+f"(d[0]), "+f"(d[1]), "+f"(d[2]), "+f"(d[3])
        : "r"(a[0]), "r"(a[1]), "r"(a[2]), "r"(a[3]), "r"(b0), "r"(b1));
}
__device__ __forceinline__ void cp16(uint32_t dst, const void* src) {
    asm volatile("cp.async.cg.shared.global [%0], [%1], 16;" :: "r"(dst), "l"(src));
}
#define CPC()  asm volatile("cp.async.commit_group;" ::: "memory")
#define CPW(n) asm volatile("cp.async.wait_group %0;" :: "n"(n) : "memory")
#define PAIRBAR(id) asm volatile("bar.sync %0, %1;" :: "r"(id), "r"(64) : "memory")

__device__ __forceinline__ uint32_t bfpack(__nv_bfloat16 a, __nv_bfloat16 b) {
    return (uint32_t)__bfloat16_as_ushort(a) | ((uint32_t)__bfloat16_as_ushort(b) << 16);
}
__device__ __forceinline__ uint32_t hpack(float a, float b) {
    __half2 h = __floats2half2_rn(a, b);
    return *(uint32_t*)&h;
}

// smem byte offsets
#define QH_O 0
#define QL_O 33792
#define KH_O 67584
#define KL_O 101376
#define VH_O 135168
#define ST_O 204800      // Os epilogue region [VH_O, VH_O+69632) overlays V
#define SMEM_BYTES 205824
// deltas
#define D_QL 33792
#define D_KL 33792

// ---------------------------------------------------------------------------
// Projection: out[b][n][o] = sum_c W[o][c] x[b][c][n] + bias (+pos for K)
// Q,K -> bf16 hi/lo token-major; V -> single fp16 channel-major.
// ---------------------------------------------------------------------------
__global__ __launch_bounds__(256) void proj_kernel(
    const float* __restrict__ x,
    const float* __restrict__ Wq, const float* __restrict__ bq,
    const float* __restrict__ Wk, const float* __restrict__ bk,
    const float* __restrict__ Wv, const float* __restrict__ bv,
    const float* __restrict__ rel_h, const float* __restrict__ rel_w)
{
    __shared__ float Xs[16][64];
    __shared__ float Ws[16][68];
    __shared__ float Ts[64][65];

    const int tid = threadIdx.x;
    const int ty = tid >> 4, tx = tid & 15;
    const int n0 = blockIdx.x * 64;
    const int o0 = blockIdx.y * 64;
    const int b = blockIdx.z / 3;
    const int which = blockIdx.z % 3;

    const float* Wm   = (which == 0) ? Wq : (which == 1) ? Wk : Wv;
    const float* bias = (which == 0) ? bq : (which == 1) ? bk : bv;
    const float* xb = x + (size_t)b * CC * NN;

    const int lcl = tid >> 4, lnf = tid & 15;
    const int lo_ = tid >> 2, lcf = tid & 3;

    float acc[4][4] = {};
    for (int c0 = 0; c0 < CC; c0 += 16) {
        float4 xv = *(const float4*)&xb[(size_t)(c0 + lcl) * NN + n0 + lnf * 4];
        float4 wv = *(const float4*)&Wm[(o0 + lo_) * CC + c0 + lcf * 4];
        *(float4*)&Xs[lcl][lnf * 4] = xv;
        Ws[lcf * 4 + 0][lo_] = wv.x;
        Ws[lcf * 4 + 1][lo_] = wv.y;
        Ws[lcf * 4 + 2][lo_] = wv.z;
        Ws[lcf * 4 + 3][lo_] = wv.w;
        __syncthreads();
        #pragma unroll
        for (int kk = 0; kk < 16; kk++) {
            float4 a4 = *(const float4*)&Xs[kk][ty * 4];
            float4 w4 = *(const float4*)&Ws[kk][tx * 4];
            float a[4] = {a4.x, a4.y, a4.z, a4.w};
            float w[4] = {w4.x, w4.y, w4.z, w4.w};
            #pragma unroll
            for (int i = 0; i < 4; i++)
                #pragma unroll
                for (int j = 0; j < 4; j++)
                    acc[i][j] += a[i] * w[j];
        }
        __syncthreads();
    }

    float bs[4];
    #pragma unroll
    for (int j = 0; j < 4; j++) bs[j] = bias[o0 + tx * 4 + j];

    if (which < 2) {
        __nv_bfloat16* H = which ? g_Kh : g_Qh;
        __nv_bfloat16* L = which ? g_Kl : g_Ql;
        #pragma unroll
        for (int i = 0; i < 4; i++) {
            int n = n0 + ty * 4 + i;
            uint32_t hw[2], lw[2];
            #pragma unroll
            for (int jj = 0; jj < 2; jj++) {
                float r0 = acc[i][jj*2]   + bs[jj*2];
                float r1 = acc[i][jj*2+1] + bs[jj*2+1];
                if (which == 1) {
                    int c0 = o0 + tx * 4 + jj*2;
                    r0 += rel_h[c0 * 64 + (n >> 6)] + rel_w[c0 * 64 + (n & 63)];
                    r1 += rel_h[(c0+1) * 64 + (n >> 6)] + rel_w[(c0+1) * 64 + (n & 63)];
                }
                __nv_bfloat16 h0 = __float2bfloat16_rn(r0), h1 = __float2bfloat16_rn(r1);
                hw[jj] = bfpack(h0, h1);
                lw[jj] = bfpack(__float2bfloat16_rn(r0 - __bfloat162float(h0)),
                                __float2bfloat16_rn(r1 - __bfloat162float(h1)));
            }
            size_t gi = ((size_t)b * NN + n) * CC + o0 + tx * 4;
            *(uint2*)&H[gi] = make_uint2(hw[0], hw[1]);
            *(uint2*)&L[gi] = make_uint2(lw[0], lw[1]);
        }
    } else {
        // V: transpose to channel-major via smem, single fp16
        #pragma unroll
        for (int i = 0; i < 4; i++)
            #pragma unroll
            for (int j = 0; j < 4; j++)
                Ts[tx * 4 + j][ty * 4 + i] = acc[i][j] + bs[j];
        __syncthreads();
        int cl = tid >> 2, n4 = tid & 3;
        uint32_t hw[8];
        #pragma unroll
        for (int k = 0; k < 8; k++)
            hw[k] = hpack(Ts[cl][n4 * 16 + 2*k], Ts[cl][n4 * 16 + 2*k + 1]);
        size_t gi = ((size_t)b * CC + o0 + cl) * NN + n0 + n4 * 16;
        *(uint4*)&g_V[gi]     = make_uint4(hw[0], hw[1], hw[2], hw[3]);
        *(uint4*)&g_V[gi + 8] = make_uint4(hw[4], hw[5], hw[6], hw[7]);
    }
}

// ---------------------------------------------------------------------------
// HMMA flash attention. QK bf16 3-split; PV single fp16 (P,V fp16).
// P in registers (S c-frag == PV A-frag). Each warp: 16q x its 32 keys x 256ch.
// Lazy rebase threshold 10 keeps p <= e^10 < fp16 max. grid (64,4), 256 thr.
// ---------------------------------------------------------------------------
__global__ __launch_bounds__(256, 1) void attn_kernel(
    const float* __restrict__ x,
    const float* __restrict__ gamma,
    float* __restrict__ out)
{
    extern __shared__ char sm[];
    const uint32_t sb = smem_u32(sm);
    const int tid = threadIdx.x;
    const int wid = tid >> 5, ln = tid & 31;
    const int g = wid & 3, h = wid >> 2;
    const int b = blockIdx.y, m0 = blockIdx.x * 64;

    float* halfM = (float*)(sm + ST_O);          // [2][64]
    float* halfS = halfM + 128;                  // [2][64]

    const __nv_bfloat16* Qhg = g_Qh + ((size_t)b * NN + m0) * CC;
    const __nv_bfloat16* Qlg = g_Ql + ((size_t)b * NN + m0) * CC;

    auto loadK = [&](int nt) {
        const char* kh = (const char*)(g_Kh + ((size_t)b * NN + nt * 64) * CC);
        const char* kl = (const char*)(g_Kl + ((size_t)b * NN + nt * 64) * CC);
        for (int q = tid; q < 2048; q += 256) {
            int row = q >> 5, seg = q & 31;
            uint32_t d = sb + KH_O + row * 528 + seg * 16;
            cp16(d,        kh + row * 512 + seg * 16);
            cp16(d + D_KL, kl + row * 512 + seg * 16);
        }
    };
    auto loadV = [&](int nt) {
        const char* vp = (const char*)(g_V + (size_t)b * CC * NN + nt * 64);
        for (int q = tid; q < 2048; q += 256) {
            int c = q >> 3, seg = q & 7;
            cp16(sb + VH_O + c * 144 + seg * 16, vp + (size_t)c * 8192 + seg * 16);
        }
    };

    // prologue: Q, K0, V0
    for (int q = tid; q < 2048; q += 256) {
        int row = q >> 5, seg = q & 31;
        uint32_t d = sb + QH_O + row * 528 + seg * 16;
        cp16(d,        (const char*)Qhg + row * 512 + seg * 16);
        cp16(d + D_QL, (const char*)Qlg + row * 512 + seg * 16);
    }
    CPC();
    loadK(0); CPC();
    loadV(0); CPC();

    // per-lane ldmatrix address components
    const uint32_t rowsel = ((ln >> 4) << 3) + (ln & 7);
    const uint32_t colsel = ((ln >> 3) & 1) << 4;
    const uint32_t asel   = (ln & 15);
    const uint32_t acol   = (ln >> 4) << 4;
    const uint32_t aQh = sb + QH_O + (16*g + asel) * 528 + acol;
    const uint32_t aQl = aQh + D_QL;
    const uint32_t bK0 = sb + KH_O + (32*h + rowsel) * 528 + colsel;
    const uint32_t bK1 = bK0 + 16 * 528;
    // V: rows = channels (144B stride, 128B keys); warp's 32 keys at byte 64*h
    const uint32_t bV  = sb + VH_O + rowsel * 144 + colsel + 64u * h;
    const int rA = 16*g + (ln >> 2), rB = rA + 8;

    float o[32][4];
    #pragma unroll
    for (int t = 0; t < 32; t++)
        #pragma unroll
        for (int j = 0; j < 4; j++) o[t][j] = 0.0f;
    float mA_base = 0.0f, mB_base = 0.0f, lA = 0.0f, lB = 0.0f;

    for (int nt = 0; nt < 64; nt++) {
        CPW(1);            // K(nt) resident; V(nt) may still be in flight
        __syncthreads();

        // ---- QK: S(64x64), bf16 3-way split ----
        float s[4][4];
        #pragma unroll
        for (int t = 0; t < 4; t++)
            #pragma unroll
            for (int j = 0; j < 4; j++) s[t][j] = 0.0f;
        #pragma unroll
        for (int kk = 0; kk < 16; kk++) {
            uint32_t ah[4], al[4], bh0[4], bh1[4], bl0[4], bl1[4];
            const uint32_t ko = kk * 32;
            ldsm4(aQh + ko, ah); ldsm4(aQl + ko, al);
            ldsm4(bK0 + ko, bh0); ldsm4(bK1 + ko, bh1);
            ldsm4(bK0 + D_KL + ko, bl0); ldsm4(bK1 + D_KL + ko, bl1);
            mma16816(s[0], ah, bh0[0], bh0[1]); mma16816(s[1], ah, bh0[2], bh0[3]);
            mma16816(s[2], ah, bh1[0], bh1[1]); mma16816(s[3], ah, bh1[2], bh1[3]);
            mma16816(s[0], ah, bl0[0], bl0[1]); mma16816(s[1], ah, bl0[2], bl0[3]);
            mma16816(s[2], ah, bl1[0], bl1[1]); mma16816(s[3], ah, bl1[2], bl1[3]);
            mma16816(s[0], al, bh0[0], bh0[1]); mma16816(s[1], al, bh0[2], bh0[3]);
            mma16816(s[2], al, bh1[0], bh1[1]); mma16816(s[3], al, bh1[2], bh1[3]);
        }
        CPW(0);                        // V(nt) done too (visible after barrier)
        __syncthreads();               // everyone done reading K
        if (nt < 63) loadK(nt + 1);
        CPC();

        // ---- softmax: stats pair-scoped; P (fp16) stays in registers ----
        float mAl = fmaxf(fmaxf(s[0][0], s[0][1]), fmaxf(s[1][0], s[1][1]));
        mAl = fmaxf(mAl, fmaxf(fmaxf(s[2][0], s[2][1]), fmaxf(s[3][0], s[3][1])));
        float mBl = fmaxf(fmaxf(s[0][2], s[0][3]), fmaxf(s[1][2], s[1][3]));
        mBl = fmaxf(mBl, fmaxf(fmaxf(s[2][2], s[2][3]), fmaxf(s[3][2], s[3][3])));
        mAl = fmaxf(mAl, __shfl_xor_sync(0xffffffffu, mAl, 1));
        mAl = fmaxf(mAl, __shfl_xor_sync(0xffffffffu, mAl, 2));
        mBl = fmaxf(mBl, __shfl_xor_sync(0xffffffffu, mBl, 1));
        mBl = fmaxf(mBl, __shfl_xor_sync(0xffffffffu, mBl, 2));
        if ((ln & 3) == 0) { halfM[h*64 + rA] = mAl; halfM[h*64 + rB] = mBl; }
        PAIRBAR(1 + g);
        float tmA = fmaxf(halfM[rA], halfM[64 + rA]);
        float tmB = fmaxf(halfM[rB], halfM[64 + rB]);
        float fA = 1.0f, fB = 1.0f;
        if (nt == 0) {
            mA_base = tmA; mB_base = tmB;
        } else {
            // threshold 10: keeps p <= e^10 = 22026 < 65504 (fp16 max)
            if (tmA > mA_base + 10.0f) { fA = __expf(mA_base - tmA); mA_base = tmA; }
            if (tmB > mB_base + 10.0f) { fB = __expf(mB_base - tmB); mB_base = tmB; }
        }

        uint32_t ph[2][4];
        float pA = 0.0f, pB = 0.0f;
        #pragma unroll
        for (int t = 0; t < 4; t++) {
            float p0 = __expf(s[t][0] - mA_base);
            float p1 = __expf(s[t][1] - mA_base);
            float p2 = __expf(s[t][2] - mB_base);
            float p3 = __expf(s[t][3] - mB_base);
            pA += p0 + p1; pB += p2 + p3;
            const int ck = t >> 1, ps = (t & 1) << 1;
            ph[ck][ps]     = hpack(p0, p1);
            ph[ck][ps + 1] = hpack(p2, p3);
        }
        pA += __shfl_xor_sync(0xffffffffu, pA, 1);
        pA += __shfl_xor_sync(0xffffffffu, pA, 2);
        pB += __shfl_xor_sync(0xffffffffu, pB, 1);
        pB += __shfl_xor_sync(0xffffffffu, pB, 2);
        if ((ln & 3) == 0) { halfS[h*64 + rA] = pA; halfS[h*64 + rB] = pB; }
        PAIRBAR(1 + g);
        lA = lA * fA + halfS[rA] + halfS[64 + rA];
        lB = lB * fB + halfS[rB] + halfS[64 + rB];

        // ---- O lazy rescale (rare) ----
        if (__ballot_sync(0xffffffffu, (fA != 1.0f) || (fB != 1.0f))) {
            #pragma unroll
            for (int t = 0; t < 32; t++) {
                o[t][0] *= fA; o[t][1] *= fA; o[t][2] *= fB; o[t][3] *= fB;
            }
        }

        // ---- PV: single fp16, partial O over this warp's 32 keys, 256 ch ----
        uint32_t vh[2][4];
        ldsm4(bV, vh[0]);
        #pragma unroll
        for (int i = 0; i < 32; i++) {
            const int tt = i >> 1, ck = i & 1;
            const int cur = i & 1, nxt = cur ^ 1;
            if (i < 31) {
                const uint32_t nb = bV + (uint32_t)((i+1) >> 1) * (16*144)
                                       + (uint32_t)((i+1) & 1) * 32;
                ldsm4(nb, vh[nxt]);
            }
            mma16816h(o[2*tt],   ph[ck], vh[cur][0], vh[cur][1]);
            mma16816h(o[2*tt+1], ph[ck], vh[cur][2], vh[cur][3]);
        }
        __syncthreads();               // all warps done reading V(nt)
        if (nt < 63) loadV(nt + 1);
        CPC();
    }

    // ---- epilogue: sum key-halves into Os, apply 1/l, residual store ----
    __syncthreads();
    const float invA = 1.0f / lA;
    const float invB = 1.0f / lB;
    float* Os = (float*)(sm + VH_O);   // [256 c][68 tok]
    if (h == 0) {
        #pragma unroll
        for (int t = 0; t < 32; t++) {
            const int c0 = 8*t + 2*(ln & 3);
            Os[c0 * 68 + rA]       = o[t][0] * invA;
            Os[(c0 + 1) * 68 + rA] = o[t][1] * invA;
            Os[c0 * 68 + rB]       = o[t][2] * invB;
            Os[(c0 + 1) * 68 + rB] = o[t][3] * invB;
        }
    }
    __syncthreads();
    if (h == 1) {
        #pragma unroll
        for (int t = 0; t < 32; t++) {
            const int c0 = 8*t + 2*(ln & 3);
            Os[c0 * 68 + rA]       += o[t][0] * invA;
            Os[(c0 + 1) * 68 + rA] += o[t][1] * invA;
            Os[c0 * 68 + rB]       += o[t][2] * invB;
            Os[(c0 + 1) * 68 + rB] += o[t][3] * invB;
        }
    }
    __syncthreads();

    const float gm = gamma[0];
    const int cc = tid >> 2, jj = tid & 3;
    #pragma unroll
    for (int cb = 0; cb < 4; cb++) {
        const int c = cb * 64 + cc;
        const size_t gbase = ((size_t)b * CC + c) * NN + m0 + jj * 16;
        #pragma unroll
        for (int v = 0; v < 4; v++) {
            float4 ov = *(float4*)&Os[c * 68 + jj * 16 + 4 * v];
            float4 xv = *(const float4*)&x[gbase + 4 * v];
            float4 rr;
            rr.x = gm * ov.x + xv.x;
            rr.y = gm * ov.y + xv.y;
            rr.z = gm * ov.z + xv.z;
            rr.w = gm * ov.w + xv.w;
            *(float4*)&out[gbase + 4 * v] = rr;
        }
    }
}

// ---------------------------------------------------------------------------
extern "C" void kernel_launch(void* const* d_in, const int* in_sizes, int n_in,
                              void* d_out, int out_size)
{
    (void)in_sizes; (void)n_in; (void)out_size;
    const float* x     = (const float*)d_in[0];
    const float* Wq    = (const float*)d_in[1];
    const float* bq    = (const float*)d_in[2];
    const float* Wk    = (const float*)d_in[3];
    const float* bk    = (const float*)d_in[4];
    const float* Wv    = (const float*)d_in[5];
    const float* bv    = (const float*)d_in[6];
    const float* rel_h = (const float*)d_in[7];
    const float* rel_w = (const float*)d_in[8];
    const float* gamma = (const float*)d_in[9];
    float* out = (float*)d_out;

    cudaFuncSetAttribute(attn_kernel,
                         cudaFuncAttributeMaxDynamicSharedMemorySize, SMEM_BYTES);

    proj_kernel<<<dim3(64, 4, 12), 256>>>(x, Wq, bq, Wk, bk, Wv, bv, rel_h, rel_w);
    attn_kernel<<<dim3(64, 4), 256, SMEM_BYTES>>>(x, gamma, out);
}